// round 9
// baseline (speedup 1.0000x reference)
#include <cuda_runtime.h>
#include <math.h>

#define NB   2048
#define NT   200
#define NE   64
#define NH1  64
#define NH2  16
#define NROWS (NB*NT)

// Scratch (device globals; no allocation allowed)
__device__ float g_x1[(size_t)NROWS * NH1];   // [B*T, 64]
__device__ float g_x2[(size_t)NROWS * NH2];   // [B*T, 16]
__device__ float g_sum1[NH1], g_sq1[NH1];
__device__ float g_sum2[NH2], g_sq2[NH2];

__device__ __forceinline__ unsigned tf32_of(float f) {
    unsigned r;
    asm("cvt.rna.tf32.f32 %0, %1;" : "=r"(r) : "f"(f));
    return r;
}
__device__ __forceinline__ void tf32_split(float a, unsigned& hi, unsigned& lo) {
    hi = tf32_of(a);
    lo = tf32_of(a - __uint_as_float(hi));
}

#define MMA_TF32(d, a0,a1,a2,a3, b0,b1) \
    asm("mma.sync.aligned.m16n8k8.row.col.f32.tf32.tf32.f32 " \
        "{%0,%1,%2,%3}, {%4,%5,%6,%7}, {%8,%9}, {%0,%1,%2,%3};" \
        : "+f"(d[0]), "+f"(d[1]), "+f"(d[2]), "+f"(d[3]) \
        : "r"(a0), "r"(a1), "r"(a2), "r"(a3), "r"(b0), "r"(b1))

__global__ void k_zero() {
    int i = threadIdx.x;
    if (i < NH1) { g_sum1[i] = 0.f; g_sq1[i] = 0.f; }
    if (i < NH2) { g_sum2[i] = 0.f; g_sq2[i] = 0.f; }
}

// ---------------------------------------------------------------------------
// Kernel A: x1 = h@Wb + cb (2-term TF32: a_hi x (b_hi + b_lo)), store x1,
// accumulate stats1. Wb packed float4 (bh0,bh1,bl0,bl1). Warp: 32r x 32c.
// 2 blocks per batch (rows 0..127 / 128..199).
// ---------------------------------------------------------------------------
__global__ __launch_bounds__(256, 3) void k_gemm1(
    const float* __restrict__ q, const float* __restrict__ hist,
    const float* __restrict__ W1, const float* __restrict__ b1)
{
    extern __shared__ __align__(16) float dsm[];
    float* s_h   = dsm;                       // [128][68] fp32 hist rows
    float* s_WbP = dsm + 128*68;              // packed Wb: 64n * 4tin * 9f4
    __shared__ float s_q[NE], s_cb[NH1], s_sum[NH1], s_sq[NH1];

    int bid = blockIdx.x, tid = threadIdx.x;
    int b = bid >> 1, half = bid & 1;
    int R0 = half ? 128 : 0;

    if (tid < NE) {
        s_q[tid] = q[b*NE + tid];
        s_cb[tid] = b1[tid];
        s_sum[tid] = 0.f; s_sq[tid] = 0.f;
    }
    __syncthreads();

    // Build Wb, split, pack
    #pragma unroll
    for (int i = 0; i < 16; i++) {
        int idx = tid + 256*i;
        int e = idx >> 6, j = idx & 63;
        float w = W1[(64+e)*64 + j] - W1[(128+e)*64 + j] + s_q[e]*W1[(192+e)*64 + j];
        unsigned wh, wl; tf32_split(w, wh, wl);
        int base = (j*4 + (e&3))*36 + ((e>>3)<<2) + ((e>>2)&1);
        s_WbP[base]     = __uint_as_float(wh);
        s_WbP[base + 2] = __uint_as_float(wl);
    }
    // cb partial sums: 4 parts x 64 j
    {
        int j = tid & 63, part = tid >> 6;
        float acc = 0.f;
        #pragma unroll
        for (int i = 0; i < 16; i++) {
            int e = part*16 + i;
            acc += s_q[e] * (W1[e*64 + j] + W1[(128+e)*64 + j]);
        }
        atomicAdd(&s_cb[j], acc);
    }
    // Stage hist rows R0..R0+127 (zeros past NT)
    #pragma unroll
    for (int i = 0; i < 8; i++) {
        int f4 = tid + 256*i;
        int r = f4 >> 4, e0 = (f4 & 15) << 2;
        int t = R0 + r;
        float4 v = (t < NT) ? *(const float4*)&hist[((size_t)(b*NT + t))*NE + e0]
                            : make_float4(0.f, 0.f, 0.f, 0.f);
        *(float4*)&s_h[r*68 + e0] = v;
    }
    __syncthreads();

    int w = tid >> 5, lane = tid & 31, g = lane >> 2, tin = lane & 3;
    int rg = w & 3, cg = w >> 2;            // rows rg*32, cols cg*32
    int rowbase = rg * 32;

    float d[2][4][4];
    #pragma unroll
    for (int mt = 0; mt < 2; mt++)
        #pragma unroll
        for (int j = 0; j < 4; j++)
            #pragma unroll
            for (int u = 0; u < 4; u++) d[mt][j][u] = 0.f;

    #pragma unroll
    for (int kt = 0; kt < 8; kt++) {
        int k0 = kt*8;
        unsigned ah[2][4];
        #pragma unroll
        for (int mt = 0; mt < 2; mt++) {
            int ar = (rowbase + mt*16 + g)*68 + k0 + tin;
            ah[mt][0] = tf32_of(s_h[ar]);
            ah[mt][1] = tf32_of(s_h[ar + 8*68]);
            ah[mt][2] = tf32_of(s_h[ar + 4]);
            ah[mt][3] = tf32_of(s_h[ar + 8*68 + 4]);
        }
        #pragma unroll
        for (int j = 0; j < 4; j++) {
            int n = cg*32 + j*8 + g;
            float4 bv = *(const float4*)&s_WbP[(n*4 + tin)*36 + kt*4];
            unsigned bh0 = __float_as_uint(bv.x), bh1 = __float_as_uint(bv.y);
            unsigned bl0 = __float_as_uint(bv.z), bl1 = __float_as_uint(bv.w);
            #pragma unroll
            for (int mt = 0; mt < 2; mt++) {
                MMA_TF32(d[mt][j], ah[mt][0],ah[mt][1],ah[mt][2],ah[mt][3], bh0,bh1);
                MMA_TF32(d[mt][j], ah[mt][0],ah[mt][1],ah[mt][2],ah[mt][3], bl0,bl1);
            }
        }
    }

    // epilogue: bias, store x1, stats (guards warp-uniform)
    #pragma unroll
    for (int mt = 0; mt < 2; mt++) {
        int base = R0 + rowbase + mt*16;
        bool okA = (base < NT);
        bool okB = (base + 8 < NT);
        if (okA) {
            int rA = base + g, rB = rA + 8;
            #pragma unroll
            for (int j = 0; j < 4; j++) {
                int c0 = cg*32 + j*8 + tin*2;
                float cb0 = s_cb[c0], cb1 = s_cb[c0+1];
                float v0 = d[mt][j][0] + cb0, v1 = d[mt][j][1] + cb1;
                float v2 = d[mt][j][2] + cb0, v3 = d[mt][j][3] + cb1;
                float sc0 = v0, sc1 = v1, qc0 = v0*v0, qc1 = v1*v1;
                *(float2*)&g_x1[(size_t)(b*NT + rA)*NH1 + c0] = make_float2(v0, v1);
                if (okB) {
                    *(float2*)&g_x1[(size_t)(b*NT + rB)*NH1 + c0] = make_float2(v2, v3);
                    sc0 += v2; sc1 += v3; qc0 += v2*v2; qc1 += v3*v3;
                }
                #pragma unroll
                for (int off = 4; off <= 16; off <<= 1) {
                    sc0 += __shfl_xor_sync(0xffffffffu, sc0, off);
                    sc1 += __shfl_xor_sync(0xffffffffu, sc1, off);
                    qc0 += __shfl_xor_sync(0xffffffffu, qc0, off);
                    qc1 += __shfl_xor_sync(0xffffffffu, qc1, off);
                }
                if (lane < 4) {
                    atomicAdd(&s_sum[c0],   sc0); atomicAdd(&s_sum[c0+1], sc1);
                    atomicAdd(&s_sq[c0],    qc0); atomicAdd(&s_sq[c0+1],  qc1);
                }
            }
        }
    }
    __syncthreads();
    if (tid < NH1) {
        atomicAdd(&g_sum1[tid], s_sum[tid]);
        atomicAdd(&g_sq1[tid],  s_sq[tid]);
    }
}

// ---------------------------------------------------------------------------
// Kernel B: x2 = dice1(x1) @ W2 + b2 (2-term TF32) + stats2. fin1 folded in.
// W2 packed float4. Warp: 32 rows x 8 cols. 128 rows/block.
// ---------------------------------------------------------------------------
__global__ __launch_bounds__(256, 4) void k_gemm2(
    const float* __restrict__ W2, const float* __restrict__ b2,
    const float* __restrict__ alpha1)
{
    __shared__ __align__(16) float s_x[128*68];     // fp32 dice1(x1) tile
    __shared__ __align__(16) float s_W2P[64*36];    // packed W2
    __shared__ float s_m1[64], s_r1[64], s_a1[64], s_b2[16];
    __shared__ float s_sum[16], s_sq[16];

    int tid = threadIdx.x;
    int row0 = blockIdx.x * 128;
    if (tid < 64) {
        float nn = (float)NROWS;
        float m = g_sum1[tid] / nn;
        float v = g_sq1[tid] / nn - m*m;
        s_m1[tid] = m;
        s_r1[tid] = rsqrtf(v + 1e-8f);
        s_a1[tid] = alpha1[tid];
    }
    if (tid < 16) { s_b2[tid] = b2[tid]; s_sum[tid] = 0.f; s_sq[tid] = 0.f; }
    #pragma unroll
    for (int i = 0; i < 4; i++) {
        int idx = tid + 256*i;
        int k = idx >> 4, n = idx & 15;
        float wv = W2[idx];
        unsigned wh, wl; tf32_split(wv, wh, wl);
        int base = (n*4 + (k&3))*36 + ((k>>3)<<2) + ((k>>2)&1);
        s_W2P[base]     = __uint_as_float(wh);
        s_W2P[base + 2] = __uint_as_float(wl);
    }
    __syncthreads();

    // stage 128x64 x1 tile with dice1 applied (batched LDGs)
    #pragma unroll
    for (int bt = 0; bt < 4; bt++) {
        float4 vr[2];
        int f4b = tid + 256*(bt*2);
        #pragma unroll
        for (int u = 0; u < 2; u++) {
            int f4 = f4b + 256*u;
            int r = f4 >> 4, e0 = (f4 & 15) << 2;
            vr[u] = *(const float4*)&g_x1[(size_t)(row0 + r)*64 + e0];
        }
        #pragma unroll
        for (int u = 0; u < 2; u++) {
            int f4 = f4b + 256*u;
            int r = f4 >> 4, e0 = (f4 & 15) << 2;
            float vv[4] = {vr[u].x, vr[u].y, vr[u].z, vr[u].w};
            #pragma unroll
            for (int uu = 0; uu < 4; uu++) {
                int j = e0 + uu;
                float xn = (vv[uu] - s_m1[j]) * s_r1[j];
                float p  = __fdividef(1.f, 1.f + __expf(-xn));
                float a  = s_a1[j];
                vv[uu] = vv[uu] * (a + (1.f - a) * p);
            }
            *(float4*)&s_x[r*68 + e0] = make_float4(vv[0], vv[1], vv[2], vv[3]);
        }
    }
    __syncthreads();

    int w = tid >> 5, lane = tid & 31, g = lane >> 2, tin = lane & 3;
    int rg = w & 3, cg = w >> 2;          // rows rg*32, cols cg*8
    int rowbase = rg * 32;

    float d[2][4];
    #pragma unroll
    for (int mt = 0; mt < 2; mt++)
        #pragma unroll
        for (int u = 0; u < 4; u++) d[mt][u] = 0.f;

    #pragma unroll
    for (int kt = 0; kt < 8; kt++) {
        int k0 = kt*8;
        unsigned ah[2][4];
        #pragma unroll
        for (int mt = 0; mt < 2; mt++) {
            int ar = (rowbase + mt*16 + g)*68 + k0 + tin;
            ah[mt][0] = tf32_of(s_x[ar]);
            ah[mt][1] = tf32_of(s_x[ar + 8*68]);
            ah[mt][2] = tf32_of(s_x[ar + 4]);
            ah[mt][3] = tf32_of(s_x[ar + 8*68 + 4]);
        }
        int n = cg*8 + g;
        float4 bv = *(const float4*)&s_W2P[(n*4 + tin)*36 + kt*4];
        unsigned bh0 = __float_as_uint(bv.x), bh1 = __float_as_uint(bv.y);
        unsigned bl0 = __float_as_uint(bv.z), bl1 = __float_as_uint(bv.w);
        #pragma unroll
        for (int mt = 0; mt < 2; mt++) {
            MMA_TF32(d[mt], ah[mt][0],ah[mt][1],ah[mt][2],ah[mt][3], bh0,bh1);
            MMA_TF32(d[mt], ah[mt][0],ah[mt][1],ah[mt][2],ah[mt][3], bl0,bl1);
        }
    }

    #pragma unroll
    for (int mt = 0; mt < 2; mt++) {
        int rA = row0 + rowbase + mt*16 + g, rB = rA + 8;
        int c0 = cg*8 + tin*2;
        float b0v = s_b2[c0], b1v = s_b2[c0+1];
        float v0 = d[mt][0] + b0v, v1 = d[mt][1] + b1v;
        float v2 = d[mt][2] + b0v, v3 = d[mt][3] + b1v;
        *(float2*)&g_x2[(size_t)rA*16 + c0] = make_float2(v0, v1);
        *(float2*)&g_x2[(size_t)rB*16 + c0] = make_float2(v2, v3);
        float sc0 = v0 + v2, sc1 = v1 + v3;
        float qc0 = v0*v0 + v2*v2, qc1 = v1*v1 + v3*v3;
        #pragma unroll
        for (int off = 4; off <= 16; off <<= 1) {
            sc0 += __shfl_xor_sync(0xffffffffu, sc0, off);
            sc1 += __shfl_xor_sync(0xffffffffu, sc1, off);
            qc0 += __shfl_xor_sync(0xffffffffu, qc0, off);
            qc1 += __shfl_xor_sync(0xffffffffu, qc1, off);
        }
        if (lane < 4) {
            atomicAdd(&s_sum[c0],   sc0); atomicAdd(&s_sum[c0+1], sc1);
            atomicAdd(&s_sq[c0],    qc0); atomicAdd(&s_sq[c0+1],  qc1);
        }
    }
    __syncthreads();
    if (tid < 16) {
        atomicAdd(&g_sum2[tid], s_sum[tid]);
        atomicAdd(&g_sq2[tid],  s_sq[tid]);
    }
}

// ---------------------------------------------------------------------------
// Kernel C: dice2 -> mask -> softmax -> score @ hist (2-term TF32 MMA) -> out
// p stored tf32-rounded in s_pH; hist pre-split into packed B planes during
// staging -> inner loop = 8 LDS + 1 LDS.128 + 2 MMA.
// ---------------------------------------------------------------------------
__global__ __launch_bounds__(256, 4) void k_final(
    const float* __restrict__ hist, const int* __restrict__ lens,
    const float* __restrict__ alpha2, float* __restrict__ out)
{
    __shared__ __align__(16) float s_pH[16][228];   // tf32-rounded p [h][t]
    __shared__ __align__(16) float s_hP[64*4*36];   // packed hist chunk
    __shared__ float s_inv[16];
    __shared__ float s_m2[16], s_r2[16], s_a2[16];

    int b = blockIdx.x, tid = threadIdx.x;
    if (tid < 16) {
        float nn = (float)NROWS;
        float m = g_sum2[tid] / nn;
        float v = g_sq2[tid] / nn - m*m;
        s_m2[tid] = m;
        s_r2[tid] = rsqrtf(v + 1e-8f);
        s_a2[tid] = alpha2[tid];
    }
    __syncthreads();
    int len = lens[b];

    // stage logits with dice2 + mask into [h][t]
    #pragma unroll
    for (int i = 0; i < 4; i++) {
        int f4 = tid + 256*i;
        if (f4 < 800) {
            int r = f4 >> 2, h0 = (f4 & 3) << 2;
            float4 v = *(const float4*)&g_x2[(size_t)(b*NT + r)*16 + h0];
            float vv[4] = {v.x, v.y, v.z, v.w};
            #pragma unroll
            for (int u = 0; u < 4; u++) {
                int hh = h0 + u;
                float xn = (vv[u] - s_m2[hh]) * s_r2[hh];
                float p  = __fdividef(1.f, 1.f + __expf(-xn));
                float a  = s_a2[hh];
                float dd = vv[u] * (a + (1.f - a) * p);
                s_pH[hh][r] = (r < len) ? 1e-9f : dd;
            }
        }
    }
    __syncthreads();

    int w = tid >> 5, lane = tid & 31;
    // softmax: warp w handles h = 2w, 2w+1; store tf32-rounded exp, sum rounded
    #pragma unroll
    for (int hh = 0; hh < 2; hh++) {
        int h = 2*w + hh;
        float m = -1e30f;
        #pragma unroll
        for (int i = 0; i < 7; i++) {
            int t = lane + 32*i;
            if (t < NT) m = fmaxf(m, s_pH[h][t]);
        }
        #pragma unroll
        for (int off = 16; off >= 1; off >>= 1)
            m = fmaxf(m, __shfl_xor_sync(0xffffffffu, m, off));
        float s = 0.f;
        #pragma unroll
        for (int i = 0; i < 7; i++) {
            int t = lane + 32*i;
            if (t < NT) {
                float ev = __uint_as_float(tf32_of(__expf(s_pH[h][t] - m)));
                s_pH[h][t] = ev;
                s += ev;
            }
        }
        #pragma unroll
        for (int off = 16; off >= 1; off >>= 1)
            s += __shfl_xor_sync(0xffffffffu, s, off);
        if (lane == 0) s_inv[h] = __fdividef(1.f, s);
    }

    // out = (1/sum) * p[16x200] @ hist[200x64] via 2-term TF32 MMA
    int gq = lane >> 2, tin = lane & 3;
    int n0 = w * 8;
    float d[4] = {0.f, 0.f, 0.f, 0.f};

    for (int ck = 0; ck < 4; ck++) {
        __syncthreads();
        int rows = (ck < 3) ? 64 : 8;
        for (int f4 = tid; f4 < rows*16; f4 += 256) {
            int r = f4 >> 4, e0 = (f4 & 15) << 2;
            float4 v = *(const float4*)&hist[(size_t)(b*NT + ck*64 + r)*64 + e0];
            float vv[4] = {v.x, v.y, v.z, v.w};
            int kslot = ((r>>3)<<2) + ((r>>2)&1);
            #pragma unroll
            for (int u = 0; u < 4; u++) {
                unsigned wh, wl; tf32_split(vv[u], wh, wl);
                int base = ((e0+u)*4 + (r&3))*36 + kslot;
                s_hP[base]     = __uint_as_float(wh);
                s_hP[base + 2] = __uint_as_float(wl);
            }
        }
        __syncthreads();
        int kts = rows >> 3;
        for (int kt = 0; kt < kts; kt++) {
            int gk = ck*64 + kt*8;
            unsigned ah0 = __float_as_uint(s_pH[gq][gk + tin]);
            unsigned ah1 = __float_as_uint(s_pH[gq+8][gk + tin]);
            unsigned ah2 = __float_as_uint(s_pH[gq][gk + tin + 4]);
            unsigned ah3 = __float_as_uint(s_pH[gq+8][gk + tin + 4]);
            float4 bv = *(const float4*)&s_hP[((n0+gq)*4 + tin)*36 + kt*4];
            unsigned bh0 = __float_as_uint(bv.x), bh1 = __float_as_uint(bv.y);
            unsigned bl0 = __float_as_uint(bv.z), bl1 = __float_as_uint(bv.w);
            MMA_TF32(d, ah0,ah1,ah2,ah3, bh0,bh1);
            MMA_TF32(d, ah0,ah1,ah2,ah3, bl0,bl1);
        }
    }

    float i0 = s_inv[gq], i1 = s_inv[gq + 8];
    int e0 = n0 + tin*2;
    *(float2*)&out[(size_t)(b*NH2 + gq    )*NE + e0] = make_float2(d[0]*i0, d[1]*i0);
    *(float2*)&out[(size_t)(b*NH2 + gq + 8)*NE + e0] = make_float2(d[2]*i1, d[3]*i1);
}

extern "C" void kernel_launch(void* const* d_in, const int* in_sizes, int n_in,
                              void* d_out, int out_size)
{
    const float* q    = (const float*)d_in[0];
    const float* hist = (const float*)d_in[1];
    const int*   lens = (const int*)  d_in[2];
    const float* W1   = (const float*)d_in[3];
    const float* b1   = (const float*)d_in[4];
    const float* a1   = (const float*)d_in[5];
    const float* W2   = (const float*)d_in[6];
    const float* b2   = (const float*)d_in[7];
    const float* a2   = (const float*)d_in[8];
    float* out = (float*)d_out;

    const int dyn1 = (128*68 + 64*144) * 4;   // 71680 B
    static int s_attr_done = 0;
    if (!s_attr_done) {
        cudaFuncSetAttribute(k_gemm1, cudaFuncAttributeMaxDynamicSharedMemorySize, dyn1);
        s_attr_done = 1;
    }

    k_zero<<<1, 64>>>();
    k_gemm1<<<2*NB, 256, dyn1>>>(q, hist, W1, b1);
    k_gemm2<<<NROWS/128, 256>>>(W2, b2, a1);
    k_final<<<NB, 256>>>(hist, lens, a2, out);
}

// round 12
// speedup vs baseline: 1.4162x; 1.4162x over previous
#include <cuda_runtime.h>
#include <math.h>

#define NB   2048
#define NT   200
#define NE   64
#define NH1  64
#define NH2  16
#define NROWS (NB*NT)

// Scratch (device globals; no allocation allowed)
__device__ float g_x1[(size_t)NROWS * NH1];   // [B*T, 64]
__device__ float g_x2[(size_t)NROWS * NH2];   // [B*T, 16]
__device__ float g_sum1[NH1], g_sq1[NH1];
__device__ float g_sum2[NH2], g_sq2[NH2];

__device__ __forceinline__ unsigned tf32_of(float f) {
    unsigned r;
    asm("cvt.rna.tf32.f32 %0, %1;" : "=r"(r) : "f"(f));
    return r;
}
__device__ __forceinline__ void tf32_split(float a, unsigned& hi, unsigned& lo) {
    hi = tf32_of(a);
    lo = tf32_of(a - __uint_as_float(hi));
}

#define MMA_TF32(d, a0,a1,a2,a3, b0,b1) \
    asm("mma.sync.aligned.m16n8k8.row.col.f32.tf32.tf32.f32 " \
        "{%0,%1,%2,%3}, {%4,%5,%6,%7}, {%8,%9}, {%0,%1,%2,%3};" \
        : "+f"(d[0]), "+f"(d[1]), "+f"(d[2]), "+f"(d[3]) \
        : "r"(a0), "r"(a1), "r"(a2), "r"(a3), "r"(b0), "r"(b1))

__global__ void k_zero() {
    int i = threadIdx.x;
    if (i < NH1) { g_sum1[i] = 0.f; g_sq1[i] = 0.f; }
    if (i < NH2) { g_sum2[i] = 0.f; g_sq2[i] = 0.f; }
}

// ---------------------------------------------------------------------------
// Kernel A: x1 = h@Wb + cb (2-term TF32: a_hi x (b_hi + b_lo)), store x1,
// accumulate stats1. Wb packed float4 (bh0,bh1,bl0,bl1). Warp: 32r x 32c.
// 2 blocks per batch (rows 0..127 / 128..199).
// ---------------------------------------------------------------------------
__global__ __launch_bounds__(256, 3) void k_gemm1(
    const float* __restrict__ q, const float* __restrict__ hist,
    const float* __restrict__ W1, const float* __restrict__ b1)
{
    extern __shared__ __align__(16) float dsm[];
    float* s_h   = dsm;                       // [128][68] fp32 hist rows
    float* s_WbP = dsm + 128*68;              // packed Wb: 64n * 4tin * 9f4
    __shared__ float s_q[NE], s_cb[NH1], s_sum[NH1], s_sq[NH1];

    int bid = blockIdx.x, tid = threadIdx.x;
    int b = bid >> 1, half = bid & 1;
    int R0 = half ? 128 : 0;

    if (tid < NE) {
        s_q[tid] = q[b*NE + tid];
        s_cb[tid] = b1[tid];
        s_sum[tid] = 0.f; s_sq[tid] = 0.f;
    }
    __syncthreads();

    // Build Wb, split, pack
    #pragma unroll
    for (int i = 0; i < 16; i++) {
        int idx = tid + 256*i;
        int e = idx >> 6, j = idx & 63;
        float w = W1[(64+e)*64 + j] - W1[(128+e)*64 + j] + s_q[e]*W1[(192+e)*64 + j];
        unsigned wh, wl; tf32_split(w, wh, wl);
        int base = (j*4 + (e&3))*36 + ((e>>3)<<2) + ((e>>2)&1);
        s_WbP[base]     = __uint_as_float(wh);
        s_WbP[base + 2] = __uint_as_float(wl);
    }
    // cb partial sums: 4 parts x 64 j
    {
        int j = tid & 63, part = tid >> 6;
        float acc = 0.f;
        #pragma unroll
        for (int i = 0; i < 16; i++) {
            int e = part*16 + i;
            acc += s_q[e] * (W1[e*64 + j] + W1[(128+e)*64 + j]);
        }
        atomicAdd(&s_cb[j], acc);
    }
    // Stage hist rows R0..R0+127 (zeros past NT)
    #pragma unroll
    for (int i = 0; i < 8; i++) {
        int f4 = tid + 256*i;
        int r = f4 >> 4, e0 = (f4 & 15) << 2;
        int t = R0 + r;
        float4 v = (t < NT) ? *(const float4*)&hist[((size_t)(b*NT + t))*NE + e0]
                            : make_float4(0.f, 0.f, 0.f, 0.f);
        *(float4*)&s_h[r*68 + e0] = v;
    }
    __syncthreads();

    int w = tid >> 5, lane = tid & 31, g = lane >> 2, tin = lane & 3;
    int rg = w & 3, cg = w >> 2;            // rows rg*32, cols cg*32
    int rowbase = rg * 32;

    float d[2][4][4];
    #pragma unroll
    for (int mt = 0; mt < 2; mt++)
        #pragma unroll
        for (int j = 0; j < 4; j++)
            #pragma unroll
            for (int u = 0; u < 4; u++) d[mt][j][u] = 0.f;

    #pragma unroll
    for (int kt = 0; kt < 8; kt++) {
        int k0 = kt*8;
        unsigned ah[2][4];
        #pragma unroll
        for (int mt = 0; mt < 2; mt++) {
            int ar = (rowbase + mt*16 + g)*68 + k0 + tin;
            ah[mt][0] = tf32_of(s_h[ar]);
            ah[mt][1] = tf32_of(s_h[ar + 8*68]);
            ah[mt][2] = tf32_of(s_h[ar + 4]);
            ah[mt][3] = tf32_of(s_h[ar + 8*68 + 4]);
        }
        #pragma unroll
        for (int j = 0; j < 4; j++) {
            int n = cg*32 + j*8 + g;
            float4 bv = *(const float4*)&s_WbP[(n*4 + tin)*36 + kt*4];
            unsigned bh0 = __float_as_uint(bv.x), bh1 = __float_as_uint(bv.y);
            unsigned bl0 = __float_as_uint(bv.z), bl1 = __float_as_uint(bv.w);
            #pragma unroll
            for (int mt = 0; mt < 2; mt++) {
                MMA_TF32(d[mt][j], ah[mt][0],ah[mt][1],ah[mt][2],ah[mt][3], bh0,bh1);
                MMA_TF32(d[mt][j], ah[mt][0],ah[mt][1],ah[mt][2],ah[mt][3], bl0,bl1);
            }
        }
    }

    // epilogue: bias, store x1, stats (guards warp-uniform)
    #pragma unroll
    for (int mt = 0; mt < 2; mt++) {
        int base = R0 + rowbase + mt*16;
        bool okA = (base < NT);
        bool okB = (base + 8 < NT);
        if (okA) {
            int rA = base + g, rB = rA + 8;
            #pragma unroll
            for (int j = 0; j < 4; j++) {
                int c0 = cg*32 + j*8 + tin*2;
                float cb0 = s_cb[c0], cb1 = s_cb[c0+1];
                float v0 = d[mt][j][0] + cb0, v1 = d[mt][j][1] + cb1;
                float v2 = d[mt][j][2] + cb0, v3 = d[mt][j][3] + cb1;
                float sc0 = v0, sc1 = v1, qc0 = v0*v0, qc1 = v1*v1;
                *(float2*)&g_x1[(size_t)(b*NT + rA)*NH1 + c0] = make_float2(v0, v1);
                if (okB) {
                    *(float2*)&g_x1[(size_t)(b*NT + rB)*NH1 + c0] = make_float2(v2, v3);
                    sc0 += v2; sc1 += v3; qc0 += v2*v2; qc1 += v3*v3;
                }
                #pragma unroll
                for (int off = 4; off <= 16; off <<= 1) {
                    sc0 += __shfl_xor_sync(0xffffffffu, sc0, off);
                    sc1 += __shfl_xor_sync(0xffffffffu, sc1, off);
                    qc0 += __shfl_xor_sync(0xffffffffu, qc0, off);
                    qc1 += __shfl_xor_sync(0xffffffffu, qc1, off);
                }
                if (lane < 4) {
                    atomicAdd(&s_sum[c0],   sc0); atomicAdd(&s_sum[c0+1], sc1);
                    atomicAdd(&s_sq[c0],    qc0); atomicAdd(&s_sq[c0+1],  qc1);
                }
            }
        }
    }
    __syncthreads();
    if (tid < NH1) {
        atomicAdd(&g_sum1[tid], s_sum[tid]);
        atomicAdd(&g_sq1[tid],  s_sq[tid]);
    }
}

// ---------------------------------------------------------------------------
// Kernel B: x2 = dice1(x1) @ W2 + b2 (2-term TF32) + stats2. fin1 folded in.
// W2 packed float4. Warp: 32 rows x 8 cols. 128 rows/block.
// ---------------------------------------------------------------------------
__global__ __launch_bounds__(256, 4) void k_gemm2(
    const float* __restrict__ W2, const float* __restrict__ b2,
    const float* __restrict__ alpha1)
{
    __shared__ __align__(16) float s_x[128*68];     // fp32 dice1(x1) tile
    __shared__ __align__(16) float s_W2P[64*36];    // packed W2
    __shared__ float s_m1[64], s_r1[64], s_a1[64], s_b2[16];
    __shared__ float s_sum[16], s_sq[16];

    int tid = threadIdx.x;
    int row0 = blockIdx.x * 128;
    if (tid < 64) {
        float nn = (float)NROWS;
        float m = g_sum1[tid] / nn;
        float v = g_sq1[tid] / nn - m*m;
        s_m1[tid] = m;
        s_r1[tid] = rsqrtf(v + 1e-8f);
        s_a1[tid] = alpha1[tid];
    }
    if (tid < 16) { s_b2[tid] = b2[tid]; s_sum[tid] = 0.f; s_sq[tid] = 0.f; }
    #pragma unroll
    for (int i = 0; i < 4; i++) {
        int idx = tid + 256*i;
        int k = idx >> 4, n = idx & 15;
        float wv = W2[idx];
        unsigned wh, wl; tf32_split(wv, wh, wl);
        int base = (n*4 + (k&3))*36 + ((k>>3)<<2) + ((k>>2)&1);
        s_W2P[base]     = __uint_as_float(wh);
        s_W2P[base + 2] = __uint_as_float(wl);
    }
    __syncthreads();

    // stage 128x64 x1 tile with dice1 applied (batched LDGs)
    #pragma unroll
    for (int bt = 0; bt < 4; bt++) {
        float4 vr[2];
        int f4b = tid + 256*(bt*2);
        #pragma unroll
        for (int u = 0; u < 2; u++) {
            int f4 = f4b + 256*u;
            int r = f4 >> 4, e0 = (f4 & 15) << 2;
            vr[u] = *(const float4*)&g_x1[(size_t)(row0 + r)*64 + e0];
        }
        #pragma unroll
        for (int u = 0; u < 2; u++) {
            int f4 = f4b + 256*u;
            int r = f4 >> 4, e0 = (f4 & 15) << 2;
            float vv[4] = {vr[u].x, vr[u].y, vr[u].z, vr[u].w};
            #pragma unroll
            for (int uu = 0; uu < 4; uu++) {
                int j = e0 + uu;
                float xn = (vv[uu] - s_m1[j]) * s_r1[j];
                float p  = __fdividef(1.f, 1.f + __expf(-xn));
                float a  = s_a1[j];
                vv[uu] = vv[uu] * (a + (1.f - a) * p);
            }
            *(float4*)&s_x[r*68 + e0] = make_float4(vv[0], vv[1], vv[2], vv[3]);
        }
    }
    __syncthreads();

    int w = tid >> 5, lane = tid & 31, g = lane >> 2, tin = lane & 3;
    int rg = w & 3, cg = w >> 2;          // rows rg*32, cols cg*8
    int rowbase = rg * 32;

    float d[2][4];
    #pragma unroll
    for (int mt = 0; mt < 2; mt++)
        #pragma unroll
        for (int u = 0; u < 4; u++) d[mt][u] = 0.f;

    #pragma unroll
    for (int kt = 0; kt < 8; kt++) {
        int k0 = kt*8;
        unsigned ah[2][4];
        #pragma unroll
        for (int mt = 0; mt < 2; mt++) {
            int ar = (rowbase + mt*16 + g)*68 + k0 + tin;
            ah[mt][0] = tf32_of(s_x[ar]);
            ah[mt][1] = tf32_of(s_x[ar + 8*68]);
            ah[mt][2] = tf32_of(s_x[ar + 4]);
            ah[mt][3] = tf32_of(s_x[ar + 8*68 + 4]);
        }
        int n = cg*8 + g;
        float4 bv = *(const float4*)&s_W2P[(n*4 + tin)*36 + kt*4];
        unsigned bh0 = __float_as_uint(bv.x), bh1 = __float_as_uint(bv.y);
        unsigned bl0 = __float_as_uint(bv.z), bl1 = __float_as_uint(bv.w);
        #pragma unroll
        for (int mt = 0; mt < 2; mt++) {
            MMA_TF32(d[mt], ah[mt][0],ah[mt][1],ah[mt][2],ah[mt][3], bh0,bh1);
            MMA_TF32(d[mt], ah[mt][0],ah[mt][1],ah[mt][2],ah[mt][3], bl0,bl1);
        }
    }

    #pragma unroll
    for (int mt = 0; mt < 2; mt++) {
        int rA = row0 + rowbase + mt*16 + g, rB = rA + 8;
        int c0 = cg*8 + tin*2;
        float b0v = s_b2[c0], b1v = s_b2[c0+1];
        float v0 = d[mt][0] + b0v, v1 = d[mt][1] + b1v;
        float v2 = d[mt][2] + b0v, v3 = d[mt][3] + b1v;
        *(float2*)&g_x2[(size_t)rA*16 + c0] = make_float2(v0, v1);
        *(float2*)&g_x2[(size_t)rB*16 + c0] = make_float2(v2, v3);
        float sc0 = v0 + v2, sc1 = v1 + v3;
        float qc0 = v0*v0 + v2*v2, qc1 = v1*v1 + v3*v3;
        #pragma unroll
        for (int off = 4; off <= 16; off <<= 1) {
            sc0 += __shfl_xor_sync(0xffffffffu, sc0, off);
            sc1 += __shfl_xor_sync(0xffffffffu, sc1, off);
            qc0 += __shfl_xor_sync(0xffffffffu, qc0, off);
            qc1 += __shfl_xor_sync(0xffffffffu, qc1, off);
        }
        if (lane < 4) {
            atomicAdd(&s_sum[c0],   sc0); atomicAdd(&s_sum[c0+1], sc1);
            atomicAdd(&s_sq[c0],    qc0); atomicAdd(&s_sq[c0+1],  qc1);
        }
    }
    __syncthreads();
    if (tid < 16) {
        atomicAdd(&g_sum2[tid], s_sum[tid]);
        atomicAdd(&g_sq2[tid],  s_sq[tid]);
    }
}

// ---------------------------------------------------------------------------
// Kernel C: dice2 -> mask -> softmax -> score @ hist (2-term TF32 MMA) -> out
// p tf32-rounded in single s_pH plane; hist staged [64][72] (conflict-free),
// B split in registers per k-step. Inner loop: 4+2 LDS, 2 cvt-splits, 2 MMA.
// ---------------------------------------------------------------------------
__global__ __launch_bounds__(256, 4) void k_final(
    const float* __restrict__ hist, const int* __restrict__ lens,
    const float* __restrict__ alpha2, float* __restrict__ out)
{
    __shared__ __align__(16) float s_pH[16][228];   // tf32-rounded p [h][t]
    __shared__ __align__(16) float s_hist[64][72];  // hist chunk [t][e]
    __shared__ float s_inv[16];
    __shared__ float s_m2[16], s_r2[16], s_a2[16];

    int b = blockIdx.x, tid = threadIdx.x;
    if (tid < 16) {
        float nn = (float)NROWS;
        float m = g_sum2[tid] / nn;
        float v = g_sq2[tid] / nn - m*m;
        s_m2[tid] = m;
        s_r2[tid] = rsqrtf(v + 1e-8f);
        s_a2[tid] = alpha2[tid];
    }
    __syncthreads();
    int len = lens[b];

    // stage logits with dice2 + mask into [h][t]
    #pragma unroll
    for (int i = 0; i < 4; i++) {
        int f4 = tid + 256*i;
        if (f4 < 800) {
            int r = f4 >> 2, h0 = (f4 & 3) << 2;
            float4 v = *(const float4*)&g_x2[(size_t)(b*NT + r)*16 + h0];
            float vv[4] = {v.x, v.y, v.z, v.w};
            #pragma unroll
            for (int u = 0; u < 4; u++) {
                int hh = h0 + u;
                float xn = (vv[u] - s_m2[hh]) * s_r2[hh];
                float p  = __fdividef(1.f, 1.f + __expf(-xn));
                float a  = s_a2[hh];
                float dd = vv[u] * (a + (1.f - a) * p);
                s_pH[hh][r] = (r < len) ? 1e-9f : dd;
            }
        }
    }
    __syncthreads();

    int w = tid >> 5, lane = tid & 31;
    // softmax: warp w handles h = 2w, 2w+1; store tf32-rounded exp, sum rounded
    #pragma unroll
    for (int hh = 0; hh < 2; hh++) {
        int h = 2*w + hh;
        float m = -1e30f;
        #pragma unroll
        for (int i = 0; i < 7; i++) {
            int t = lane + 32*i;
            if (t < NT) m = fmaxf(m, s_pH[h][t]);
        }
        #pragma unroll
        for (int off = 16; off >= 1; off >>= 1)
            m = fmaxf(m, __shfl_xor_sync(0xffffffffu, m, off));
        float s = 0.f;
        #pragma unroll
        for (int i = 0; i < 7; i++) {
            int t = lane + 32*i;
            if (t < NT) {
                float ev = __uint_as_float(tf32_of(__expf(s_pH[h][t] - m)));
                s_pH[h][t] = ev;
                s += ev;
            }
        }
        #pragma unroll
        for (int off = 16; off >= 1; off >>= 1)
            s += __shfl_xor_sync(0xffffffffu, s, off);
        if (lane == 0) s_inv[h] = __fdividef(1.f, s);
    }

    // out = (1/sum) * p[16x200] @ hist[200x64] via 2-term TF32 MMA
    int gq = lane >> 2, tin = lane & 3;
    int n0 = w * 8;
    float d[4] = {0.f, 0.f, 0.f, 0.f};

    for (int ck = 0; ck < 4; ck++) {
        __syncthreads();
        int rows = (ck < 3) ? 64 : 8;
        for (int f4 = tid; f4 < rows*16; f4 += 256) {
            int r = f4 >> 4, e0 = (f4 & 15) << 2;
            *(float4*)&s_hist[r][e0] =
                *(const float4*)&hist[(size_t)(b*NT + ck*64 + r)*64 + e0];
        }
        __syncthreads();
        int kts = rows >> 3;
        for (int kt = 0; kt < kts; kt++) {
            int k0 = kt*8, gk = ck*64 + k0;
            unsigned ah0 = __float_as_uint(s_pH[gq][gk + tin]);
            unsigned ah1 = __float_as_uint(s_pH[gq+8][gk + tin]);
            unsigned ah2 = __float_as_uint(s_pH[gq][gk + tin + 4]);
            unsigned ah3 = __float_as_uint(s_pH[gq+8][gk + tin + 4]);
            float b0f = s_hist[k0 + tin][n0 + gq];
            float b1f = s_hist[k0 + tin + 4][n0 + gq];
            unsigned bh0,bl0,bh1,bl1;
            tf32_split(b0f, bh0, bl0); tf32_split(b1f, bh1, bl1);
            MMA_TF32(d, ah0,ah1,ah2,ah3, bh0,bh1);
            MMA_TF32(d, ah0,ah1,ah2,ah3, bl0,bl1);
        }
    }

    float i0 = s_inv[gq], i1 = s_inv[gq + 8];
    int e0 = n0 + tin*2;
    *(float2*)&out[(size_t)(b*NH2 + gq    )*NE + e0] = make_float2(d[0]*i0, d[1]*i0);
    *(float2*)&out[(size_t)(b*NH2 + gq + 8)*NE + e0] = make_float2(d[2]*i1, d[3]*i1);
}

extern "C" void kernel_launch(void* const* d_in, const int* in_sizes, int n_in,
                              void* d_out, int out_size)
{
    const float* q    = (const float*)d_in[0];
    const float* hist = (const float*)d_in[1];
    const int*   lens = (const int*)  d_in[2];
    const float* W1   = (const float*)d_in[3];
    const float* b1   = (const float*)d_in[4];
    const float* a1   = (const float*)d_in[5];
    const float* W2   = (const float*)d_in[6];
    const float* b2   = (const float*)d_in[7];
    const float* a2   = (const float*)d_in[8];
    float* out = (float*)d_out;

    const int dyn1 = (128*68 + 64*144) * 4;   // 71680 B
    static int s_attr_done = 0;
    if (!s_attr_done) {
        cudaFuncSetAttribute(k_gemm1, cudaFuncAttributeMaxDynamicSharedMemorySize, dyn1);
        s_attr_done = 1;
    }

    k_zero<<<1, 64>>>();
    k_gemm1<<<2*NB, 256, dyn1>>>(q, hist, W1, b1);
    k_gemm2<<<NROWS/128, 256>>>(W2, b2, a1);
    k_final<<<NB, 256>>>(hist, lens, a2, out);
}

// round 13
// speedup vs baseline: 1.4494x; 1.0234x over previous
#include <cuda_runtime.h>
#include <math.h>

#define NB   2048
#define NT   200
#define NE   64
#define NH1  64
#define NH2  16
#define NROWS (NB*NT)

// Scratch (device globals; no allocation allowed)
__device__ float g_x1[(size_t)NROWS * NH1];   // [B*T, 64]
__device__ float g_x2[(size_t)NROWS * NH2];   // [B*T, 16]
__device__ float g_CB[(size_t)NB * NH1];      // per-batch effective bias
__device__ float g_D1[NE * NH1];              // W1b - W1c
__device__ float g_sum1[NH1], g_sq1[NH1];
__device__ float g_sum2[NH2], g_sq2[NH2];

__device__ __forceinline__ unsigned tf32_of(float f) {
    unsigned r;
    asm("cvt.rna.tf32.f32 %0, %1;" : "=r"(r) : "f"(f));
    return r;
}
__device__ __forceinline__ void tf32_split(float a, unsigned& hi, unsigned& lo) {
    hi = tf32_of(a);
    lo = tf32_of(a - __uint_as_float(hi));
}

#define MMA_TF32(d, a0,a1,a2,a3, b0,b1) \
    asm("mma.sync.aligned.m16n8k8.row.col.f32.tf32.tf32.f32 " \
        "{%0,%1,%2,%3}, {%4,%5,%6,%7}, {%8,%9}, {%0,%1,%2,%3};" \
        : "+f"(d[0]), "+f"(d[1]), "+f"(d[2]), "+f"(d[3]) \
        : "r"(a0), "r"(a1), "r"(a2), "r"(a3), "r"(b0), "r"(b1))

__global__ void k_zero() {
    int i = threadIdx.x;
    if (i < NH1) { g_sum1[i] = 0.f; g_sq1[i] = 0.f; }
    if (i < NH2) { g_sum2[i] = 0.f; g_sq2[i] = 0.f; }
}

// ---------------------------------------------------------------------------
// k_prep: CB[b][j] = b1[j] + sum_e q[b][e]*(W1a+W1c)[e][j]  for all batches;
// D1 = W1b - W1c. 128 blocks x 256 threads; 16 batches per block.
// ---------------------------------------------------------------------------
__global__ __launch_bounds__(256, 4) void k_prep(
    const float* __restrict__ q, const float* __restrict__ W1,
    const float* __restrict__ b1)
{
    __shared__ float s_S[64*64];     // (W1a + W1c)[e][j]
    __shared__ float s_qt[16*64];    // q rows for this block's batches

    int tid = threadIdx.x, bb0 = blockIdx.x * 16;

    if (blockIdx.x < 16) {
        int idx = blockIdx.x*256 + tid;
        g_D1[idx] = W1[4096 + idx] - W1[8192 + idx];
    }
    #pragma unroll
    for (int i = 0; i < 16; i++) {
        int idx = tid + 256*i;
        s_S[idx] = W1[idx] + W1[8192 + idx];
    }
    #pragma unroll
    for (int i = 0; i < 4; i++) {
        int idx = tid + 256*i;
        s_qt[idx] = q[(size_t)bb0*64 + idx];
    }
    __syncthreads();

    int j = tid & 63, bg = tid >> 6;          // thread -> (j, 4 batches)
    float acc[4] = {0.f, 0.f, 0.f, 0.f};
    #pragma unroll 8
    for (int e = 0; e < 64; e++) {
        float sv = s_S[e*64 + j];
        #pragma unroll
        for (int u = 0; u < 4; u++)
            acc[u] = fmaf(s_qt[(bg*4 + u)*64 + e], sv, acc[u]);
    }
    float bj = b1[j];
    #pragma unroll
    for (int u = 0; u < 4; u++)
        g_CB[(size_t)(bb0 + bg*4 + u)*64 + j] = acc[u] + bj;
}

// ---------------------------------------------------------------------------
// Kernel A: x1 = h@Wb + cb (2-term TF32: a_hi x (b_hi + b_lo)), store x1,
// accumulate stats1. Wb = D1 + q*W1d (2 LDG/elem); cb read from g_CB.
// Wb packed float4 (bh0,bh1,bl0,bl1). Warp: 32r x 32c.
// 2 blocks per batch (rows 0..127 / 128..199).
// ---------------------------------------------------------------------------
__global__ __launch_bounds__(256, 3) void k_gemm1(
    const float* __restrict__ q, const float* __restrict__ hist,
    const float* __restrict__ W1, const float* __restrict__ b1)
{
    extern __shared__ __align__(16) float dsm[];
    float* s_h   = dsm;                       // [128][68] fp32 hist rows
    float* s_WbP = dsm + 128*68;              // packed Wb: 64n * 4tin * 9f4
    __shared__ float s_q[NE], s_cb[NH1], s_sum[NH1], s_sq[NH1];

    int bid = blockIdx.x, tid = threadIdx.x;
    int b = bid >> 1, half = bid & 1;
    int R0 = half ? 128 : 0;

    if (tid < NE) {
        s_q[tid] = q[b*NE + tid];
        s_cb[tid] = g_CB[(size_t)b*64 + tid];
        s_sum[tid] = 0.f; s_sq[tid] = 0.f;
    }
    __syncthreads();

    // Build Wb = D1 + q*W1d, split, pack
    #pragma unroll
    for (int i = 0; i < 16; i++) {
        int idx = tid + 256*i;
        int e = idx >> 6, j = idx & 63;
        float w = g_D1[idx] + s_q[e]*W1[12288 + idx];
        unsigned wh, wl; tf32_split(w, wh, wl);
        int base = (j*4 + (e&3))*36 + ((e>>3)<<2) + ((e>>2)&1);
        s_WbP[base]     = __uint_as_float(wh);
        s_WbP[base + 2] = __uint_as_float(wl);
    }
    // Stage hist rows R0..R0+127 (zeros past NT)
    #pragma unroll
    for (int i = 0; i < 8; i++) {
        int f4 = tid + 256*i;
        int r = f4 >> 4, e0 = (f4 & 15) << 2;
        int t = R0 + r;
        float4 v = (t < NT) ? *(const float4*)&hist[((size_t)(b*NT + t))*NE + e0]
                            : make_float4(0.f, 0.f, 0.f, 0.f);
        *(float4*)&s_h[r*68 + e0] = v;
    }
    __syncthreads();

    int w = tid >> 5, lane = tid & 31, g = lane >> 2, tin = lane & 3;
    int rg = w & 3, cg = w >> 2;            // rows rg*32, cols cg*32
    int rowbase = rg * 32;

    float d[2][4][4];
    #pragma unroll
    for (int mt = 0; mt < 2; mt++)
        #pragma unroll
        for (int j = 0; j < 4; j++)
            #pragma unroll
            for (int u = 0; u < 4; u++) d[mt][j][u] = 0.f;

    #pragma unroll
    for (int kt = 0; kt < 8; kt++) {
        int k0 = kt*8;
        unsigned ah[2][4];
        #pragma unroll
        for (int mt = 0; mt < 2; mt++) {
            int ar = (rowbase + mt*16 + g)*68 + k0 + tin;
            ah[mt][0] = tf32_of(s_h[ar]);
            ah[mt][1] = tf32_of(s_h[ar + 8*68]);
            ah[mt][2] = tf32_of(s_h[ar + 4]);
            ah[mt][3] = tf32_of(s_h[ar + 8*68 + 4]);
        }
        #pragma unroll
        for (int j = 0; j < 4; j++) {
            int n = cg*32 + j*8 + g;
            float4 bv = *(const float4*)&s_WbP[(n*4 + tin)*36 + kt*4];
            unsigned bh0 = __float_as_uint(bv.x), bh1 = __float_as_uint(bv.y);
            unsigned bl0 = __float_as_uint(bv.z), bl1 = __float_as_uint(bv.w);
            #pragma unroll
            for (int mt = 0; mt < 2; mt++) {
                MMA_TF32(d[mt][j], ah[mt][0],ah[mt][1],ah[mt][2],ah[mt][3], bh0,bh1);
                MMA_TF32(d[mt][j], ah[mt][0],ah[mt][1],ah[mt][2],ah[mt][3], bl0,bl1);
            }
        }
    }

    // epilogue: bias, store x1, stats (guards warp-uniform)
    #pragma unroll
    for (int mt = 0; mt < 2; mt++) {
        int base = R0 + rowbase + mt*16;
        bool okA = (base < NT);
        bool okB = (base + 8 < NT);
        if (okA) {
            int rA = base + g, rB = rA + 8;
            #pragma unroll
            for (int j = 0; j < 4; j++) {
                int c0 = cg*32 + j*8 + tin*2;
                float cb0 = s_cb[c0], cb1 = s_cb[c0+1];
                float v0 = d[mt][j][0] + cb0, v1 = d[mt][j][1] + cb1;
                float v2 = d[mt][j][2] + cb0, v3 = d[mt][j][3] + cb1;
                float sc0 = v0, sc1 = v1, qc0 = v0*v0, qc1 = v1*v1;
                *(float2*)&g_x1[(size_t)(b*NT + rA)*NH1 + c0] = make_float2(v0, v1);
                if (okB) {
                    *(float2*)&g_x1[(size_t)(b*NT + rB)*NH1 + c0] = make_float2(v2, v3);
                    sc0 += v2; sc1 += v3; qc0 += v2*v2; qc1 += v3*v3;
                }
                #pragma unroll
                for (int off = 4; off <= 16; off <<= 1) {
                    sc0 += __shfl_xor_sync(0xffffffffu, sc0, off);
                    sc1 += __shfl_xor_sync(0xffffffffu, sc1, off);
                    qc0 += __shfl_xor_sync(0xffffffffu, qc0, off);
                    qc1 += __shfl_xor_sync(0xffffffffu, qc1, off);
                }
                if (lane < 4) {
                    atomicAdd(&s_sum[c0],   sc0); atomicAdd(&s_sum[c0+1], sc1);
                    atomicAdd(&s_sq[c0],    qc0); atomicAdd(&s_sq[c0+1],  qc1);
                }
            }
        }
    }
    __syncthreads();
    if (tid < NH1) {
        atomicAdd(&g_sum1[tid], s_sum[tid]);
        atomicAdd(&g_sq1[tid],  s_sq[tid]);
    }
}

// ---------------------------------------------------------------------------
// Kernel B: x2 = dice1(x1) @ W2 + b2 (2-term TF32) + stats2. fin1 folded in.
// W2 packed float4. Warp: 32 rows x 8 cols. 128 rows/block.
// ---------------------------------------------------------------------------
__global__ __launch_bounds__(256, 4) void k_gemm2(
    const float* __restrict__ W2, const float* __restrict__ b2,
    const float* __restrict__ alpha1)
{
    __shared__ __align__(16) float s_x[128*68];     // fp32 dice1(x1) tile
    __shared__ __align__(16) float s_W2P[64*36];    // packed W2
    __shared__ float s_m1[64], s_r1[64], s_a1[64], s_b2[16];
    __shared__ float s_sum[16], s_sq[16];

    int tid = threadIdx.x;
    int row0 = blockIdx.x * 128;
    if (tid < 64) {
        float nn = (float)NROWS;
        float m = g_sum1[tid] / nn;
        float v = g_sq1[tid] / nn - m*m;
        s_m1[tid] = m;
        s_r1[tid] = rsqrtf(v + 1e-8f);
        s_a1[tid] = alpha1[tid];
    }
    if (tid < 16) { s_b2[tid] = b2[tid]; s_sum[tid] = 0.f; s_sq[tid] = 0.f; }
    #pragma unroll
    for (int i = 0; i < 4; i++) {
        int idx = tid + 256*i;
        int k = idx >> 4, n = idx & 15;
        float wv = W2[idx];
        unsigned wh, wl; tf32_split(wv, wh, wl);
        int base = (n*4 + (k&3))*36 + ((k>>3)<<2) + ((k>>2)&1);
        s_W2P[base]     = __uint_as_float(wh);
        s_W2P[base + 2] = __uint_as_float(wl);
    }
    __syncthreads();

    // stage 128x64 x1 tile with dice1 applied (batched LDGs)
    #pragma unroll
    for (int bt = 0; bt < 4; bt++) {
        float4 vr[2];
        int f4b = tid + 256*(bt*2);
        #pragma unroll
        for (int u = 0; u < 2; u++) {
            int f4 = f4b + 256*u;
            int r = f4 >> 4, e0 = (f4 & 15) << 2;
            vr[u] = *(const float4*)&g_x1[(size_t)(row0 + r)*64 + e0];
        }
        #pragma unroll
        for (int u = 0; u < 2; u++) {
            int f4 = f4b + 256*u;
            int r = f4 >> 4, e0 = (f4 & 15) << 2;
            float vv[4] = {vr[u].x, vr[u].y, vr[u].z, vr[u].w};
            #pragma unroll
            for (int uu = 0; uu < 4; uu++) {
                int j = e0 + uu;
                float xn = (vv[uu] - s_m1[j]) * s_r1[j];
                float p  = __fdividef(1.f, 1.f + __expf(-xn));
                float a  = s_a1[j];
                vv[uu] = vv[uu] * (a + (1.f - a) * p);
            }
            *(float4*)&s_x[r*68 + e0] = make_float4(vv[0], vv[1], vv[2], vv[3]);
        }
    }
    __syncthreads();

    int w = tid >> 5, lane = tid & 31, g = lane >> 2, tin = lane & 3;
    int rg = w & 3, cg = w >> 2;          // rows rg*32, cols cg*8
    int rowbase = rg * 32;

    float d[2][4];
    #pragma unroll
    for (int mt = 0; mt < 2; mt++)
        #pragma unroll
        for (int u = 0; u < 4; u++) d[mt][u] = 0.f;

    #pragma unroll
    for (int kt = 0; kt < 8; kt++) {
        int k0 = kt*8;
        unsigned ah[2][4];
        #pragma unroll
        for (int mt = 0; mt < 2; mt++) {
            int ar = (rowbase + mt*16 + g)*68 + k0 + tin;
            ah[mt][0] = tf32_of(s_x[ar]);
            ah[mt][1] = tf32_of(s_x[ar + 8*68]);
            ah[mt][2] = tf32_of(s_x[ar + 4]);
            ah[mt][3] = tf32_of(s_x[ar + 8*68 + 4]);
        }
        int n = cg*8 + g;
        float4 bv = *(const float4*)&s_W2P[(n*4 + tin)*36 + kt*4];
        unsigned bh0 = __float_as_uint(bv.x), bh1 = __float_as_uint(bv.y);
        unsigned bl0 = __float_as_uint(bv.z), bl1 = __float_as_uint(bv.w);
        #pragma unroll
        for (int mt = 0; mt < 2; mt++) {
            MMA_TF32(d[mt], ah[mt][0],ah[mt][1],ah[mt][2],ah[mt][3], bh0,bh1);
            MMA_TF32(d[mt], ah[mt][0],ah[mt][1],ah[mt][2],ah[mt][3], bl0,bl1);
        }
    }

    #pragma unroll
    for (int mt = 0; mt < 2; mt++) {
        int rA = row0 + rowbase + mt*16 + g, rB = rA + 8;
        int c0 = cg*8 + tin*2;
        float b0v = s_b2[c0], b1v = s_b2[c0+1];
        float v0 = d[mt][0] + b0v, v1 = d[mt][1] + b1v;
        float v2 = d[mt][2] + b0v, v3 = d[mt][3] + b1v;
        *(float2*)&g_x2[(size_t)rA*16 + c0] = make_float2(v0, v1);
        *(float2*)&g_x2[(size_t)rB*16 + c0] = make_float2(v2, v3);
        float sc0 = v0 + v2, sc1 = v1 + v3;
        float qc0 = v0*v0 + v2*v2, qc1 = v1*v1 + v3*v3;
        #pragma unroll
        for (int off = 4; off <= 16; off <<= 1) {
            sc0 += __shfl_xor_sync(0xffffffffu, sc0, off);
            sc1 += __shfl_xor_sync(0xffffffffu, sc1, off);
            qc0 += __shfl_xor_sync(0xffffffffu, qc0, off);
            qc1 += __shfl_xor_sync(0xffffffffu, qc1, off);
        }
        if (lane < 4) {
            atomicAdd(&s_sum[c0],   sc0); atomicAdd(&s_sum[c0+1], sc1);
            atomicAdd(&s_sq[c0],    qc0); atomicAdd(&s_sq[c0+1],  qc1);
        }
    }
    __syncthreads();
    if (tid < 16) {
        atomicAdd(&g_sum2[tid], s_sum[tid]);
        atomicAdd(&g_sq2[tid],  s_sq[tid]);
    }
}

// ---------------------------------------------------------------------------
// Kernel C: dice2 -> mask -> softmax -> score @ hist (2-term TF32 MMA) -> out
// p tf32-rounded in single s_pH plane; hist staged [64][72] (conflict-free),
// B split in registers per k-step.
// ---------------------------------------------------------------------------
__global__ __launch_bounds__(256, 4) void k_final(
    const float* __restrict__ hist, const int* __restrict__ lens,
    const float* __restrict__ alpha2, float* __restrict__ out)
{
    __shared__ __align__(16) float s_pH[16][228];   // tf32-rounded p [h][t]
    __shared__ __align__(16) float s_hist[64][72];  // hist chunk [t][e]
    __shared__ float s_inv[16];
    __shared__ float s_m2[16], s_r2[16], s_a2[16];

    int b = blockIdx.x, tid = threadIdx.x;
    if (tid < 16) {
        float nn = (float)NROWS;
        float m = g_sum2[tid] / nn;
        float v = g_sq2[tid] / nn - m*m;
        s_m2[tid] = m;
        s_r2[tid] = rsqrtf(v + 1e-8f);
        s_a2[tid] = alpha2[tid];
    }
    __syncthreads();
    int len = lens[b];

    // stage logits with dice2 + mask into [h][t]
    #pragma unroll
    for (int i = 0; i < 4; i++) {
        int f4 = tid + 256*i;
        if (f4 < 800) {
            int r = f4 >> 2, h0 = (f4 & 3) << 2;
            float4 v = *(const float4*)&g_x2[(size_t)(b*NT + r)*16 + h0];
            float vv[4] = {v.x, v.y, v.z, v.w};
            #pragma unroll
            for (int u = 0; u < 4; u++) {
                int hh = h0 + u;
                float xn = (vv[u] - s_m2[hh]) * s_r2[hh];
                float p  = __fdividef(1.f, 1.f + __expf(-xn));
                float a  = s_a2[hh];
                float dd = vv[u] * (a + (1.f - a) * p);
                s_pH[hh][r] = (r < len) ? 1e-9f : dd;
            }
        }
    }
    __syncthreads();

    int w = tid >> 5, lane = tid & 31;
    // softmax: warp w handles h = 2w, 2w+1; store tf32-rounded exp, sum rounded
    #pragma unroll
    for (int hh = 0; hh < 2; hh++) {
        int h = 2*w + hh;
        float m = -1e30f;
        #pragma unroll
        for (int i = 0; i < 7; i++) {
            int t = lane + 32*i;
            if (t < NT) m = fmaxf(m, s_pH[h][t]);
        }
        #pragma unroll
        for (int off = 16; off >= 1; off >>= 1)
            m = fmaxf(m, __shfl_xor_sync(0xffffffffu, m, off));
        float s = 0.f;
        #pragma unroll
        for (int i = 0; i < 7; i++) {
            int t = lane + 32*i;
            if (t < NT) {
                float ev = __uint_as_float(tf32_of(__expf(s_pH[h][t] - m)));
                s_pH[h][t] = ev;
                s += ev;
            }
        }
        #pragma unroll
        for (int off = 16; off >= 1; off >>= 1)
            s += __shfl_xor_sync(0xffffffffu, s, off);
        if (lane == 0) s_inv[h] = __fdividef(1.f, s);
    }

    // out = (1/sum) * p[16x200] @ hist[200x64] via 2-term TF32 MMA
    int gq = lane >> 2, tin = lane & 3;
    int n0 = w * 8;
    float d[4] = {0.f, 0.f, 0.f, 0.f};

    for (int ck = 0; ck < 4; ck++) {
        __syncthreads();
        int rows = (ck < 3) ? 64 : 8;
        for (int f4 = tid; f4 < rows*16; f4 += 256) {
            int r = f4 >> 4, e0 = (f4 & 15) << 2;
            *(float4*)&s_hist[r][e0] =
                *(const float4*)&hist[(size_t)(b*NT + ck*64 + r)*64 + e0];
        }
        __syncthreads();
        int kts = rows >> 3;
        for (int kt = 0; kt < kts; kt++) {
            int k0 = kt*8, gk = ck*64 + k0;
            unsigned ah0 = __float_as_uint(s_pH[gq][gk + tin]);
            unsigned ah1 = __float_as_uint(s_pH[gq+8][gk + tin]);
            unsigned ah2 = __float_as_uint(s_pH[gq][gk + tin + 4]);
            unsigned ah3 = __float_as_uint(s_pH[gq+8][gk + tin + 4]);
            float b0f = s_hist[k0 + tin][n0 + gq];
            float b1f = s_hist[k0 + tin + 4][n0 + gq];
            unsigned bh0,bl0,bh1,bl1;
            tf32_split(b0f, bh0, bl0); tf32_split(b1f, bh1, bl1);
            MMA_TF32(d, ah0,ah1,ah2,ah3, bh0,bh1);
            MMA_TF32(d, ah0,ah1,ah2,ah3, bl0,bl1);
        }
    }

    float i0 = s_inv[gq], i1 = s_inv[gq + 8];
    int e0 = n0 + tin*2;
    *(float2*)&out[(size_t)(b*NH2 + gq    )*NE + e0] = make_float2(d[0]*i0, d[1]*i0);
    *(float2*)&out[(size_t)(b*NH2 + gq + 8)*NE + e0] = make_float2(d[2]*i1, d[3]*i1);
}

extern "C" void kernel_launch(void* const* d_in, const int* in_sizes, int n_in,
                              void* d_out, int out_size)
{
    const float* q    = (const float*)d_in[0];
    const float* hist = (const float*)d_in[1];
    const int*   lens = (const int*)  d_in[2];
    const float* W1   = (const float*)d_in[3];
    const float* b1   = (const float*)d_in[4];
    const float* a1   = (const float*)d_in[5];
    const float* W2   = (const float*)d_in[6];
    const float* b2   = (const float*)d_in[7];
    const float* a2   = (const float*)d_in[8];
    float* out = (float*)d_out;

    const int dyn1 = (128*68 + 64*144) * 4;   // 71680 B
    static int s_attr_done = 0;
    if (!s_attr_done) {
        cudaFuncSetAttribute(k_gemm1, cudaFuncAttributeMaxDynamicSharedMemorySize, dyn1);
        s_attr_done = 1;
    }

    k_zero<<<1, 64>>>();
    k_prep<<<NB/16, 256>>>(q, W1, b1);
    k_gemm1<<<2*NB, 256, dyn1>>>(q, hist, W1, b1);
    k_gemm2<<<NROWS/128, 256>>>(W2, b2, a1);
    k_final<<<NB, 256>>>(hist, lens, a2, out);
}

// round 14
// speedup vs baseline: 1.5018x; 1.0362x over previous
#include <cuda_runtime.h>
#include <math.h>

#define NB   2048
#define NT   200
#define NE   64
#define NH1  64
#define NH2  16
#define NROWS (NB*NT)

// Scratch (device globals; no allocation allowed)
__device__ float g_x1[(size_t)NROWS * NH1];   // [B*T, 64]
__device__ float g_x2[(size_t)NROWS * NH2];   // [B*T, 16]
__device__ float g_CB[(size_t)NB * NH1];      // per-batch effective bias
__device__ float g_D1[NE * NH1];              // W1b - W1c
__device__ float g_sum1[NH1], g_sq1[NH1];
__device__ float g_sum2[NH2], g_sq2[NH2];

__device__ __forceinline__ unsigned tf32_of(float f) {
    unsigned r;
    asm("cvt.rna.tf32.f32 %0, %1;" : "=r"(r) : "f"(f));
    return r;
}
__device__ __forceinline__ void tf32_split(float a, unsigned& hi, unsigned& lo) {
    hi = tf32_of(a);
    lo = tf32_of(a - __uint_as_float(hi));
}

#define MMA_TF32(d, a0,a1,a2,a3, b0,b1) \
    asm("mma.sync.aligned.m16n8k8.row.col.f32.tf32.tf32.f32 " \
        "{%0,%1,%2,%3}, {%4,%5,%6,%7}, {%8,%9}, {%0,%1,%2,%3};" \
        : "+f"(d[0]), "+f"(d[1]), "+f"(d[2]), "+f"(d[3]) \
        : "r"(a0), "r"(a1), "r"(a2), "r"(a3), "r"(b0), "r"(b1))

__global__ void k_zero() {
    int i = threadIdx.x;
    if (i < NH1) { g_sum1[i] = 0.f; g_sq1[i] = 0.f; }
    if (i < NH2) { g_sum2[i] = 0.f; g_sq2[i] = 0.f; }
}

// ---------------------------------------------------------------------------
// k_prep: CB[b][j] = b1[j] + sum_e q[b][e]*(W1a+W1c)[e][j]  for all batches;
// D1 = W1b - W1c. 128 blocks x 256 threads; 16 batches per block.
// ---------------------------------------------------------------------------
__global__ __launch_bounds__(256, 4) void k_prep(
    const float* __restrict__ q, const float* __restrict__ W1,
    const float* __restrict__ b1)
{
    __shared__ float s_S[64*64];     // (W1a + W1c)[e][j]
    __shared__ float s_qt[16*64];    // q rows for this block's batches

    int tid = threadIdx.x, bb0 = blockIdx.x * 16;

    if (blockIdx.x < 16) {
        int idx = blockIdx.x*256 + tid;
        g_D1[idx] = W1[4096 + idx] - W1[8192 + idx];
    }
    #pragma unroll
    for (int i = 0; i < 16; i++) {
        int idx = tid + 256*i;
        s_S[idx] = W1[idx] + W1[8192 + idx];
    }
    #pragma unroll
    for (int i = 0; i < 4; i++) {
        int idx = tid + 256*i;
        s_qt[idx] = q[(size_t)bb0*64 + idx];
    }
    __syncthreads();

    int j = tid & 63, bg = tid >> 6;          // thread -> (j, 4 batches)
    float acc[4] = {0.f, 0.f, 0.f, 0.f};
    #pragma unroll 8
    for (int e = 0; e < 64; e++) {
        float sv = s_S[e*64 + j];
        #pragma unroll
        for (int u = 0; u < 4; u++)
            acc[u] = fmaf(s_qt[(bg*4 + u)*64 + e], sv, acc[u]);
    }
    float bj = b1[j];
    #pragma unroll
    for (int u = 0; u < 4; u++)
        g_CB[(size_t)(bb0 + bg*4 + u)*64 + j] = acc[u] + bj;
}

// ---------------------------------------------------------------------------
// Kernel A: x1 = h@Wb + cb (2-term TF32: a_hi x (b_hi + b_lo)), store x1,
// accumulate stats1. Wb = D1 + q*W1d; cb from g_CB.
// Wb in TWO planes [e][j] stride 72: conflict-free STS and LDS.
// Warp tile: 32 rows (rg) x 32 cols (cg). 2 blocks per batch.
// ---------------------------------------------------------------------------
__global__ __launch_bounds__(256, 3) void k_gemm1(
    const float* __restrict__ q, const float* __restrict__ hist,
    const float* __restrict__ W1, const float* __restrict__ b1)
{
    extern __shared__ __align__(16) float dsm[];
    float* s_h   = dsm;                       // [128][68] fp32 hist rows
    float* s_WbH = dsm + 128*68;              // [64][72] tf32-hi Wb (K-major)
    float* s_WbL = s_WbH + 64*72;             // [64][72] tf32-lo Wb
    __shared__ float s_q[NE], s_cb[NH1], s_sum[NH1], s_sq[NH1];

    int bid = blockIdx.x, tid = threadIdx.x;
    int b = bid >> 1, half = bid & 1;
    int R0 = half ? 128 : 0;

    if (tid < NE) {
        s_q[tid] = q[b*NE + tid];
        s_cb[tid] = g_CB[(size_t)b*64 + tid];
        s_sum[tid] = 0.f; s_sq[tid] = 0.f;
    }
    __syncthreads();

    // Build Wb = D1 + q*W1d, split into hi/lo planes (conflict-free stores)
    #pragma unroll
    for (int i = 0; i < 16; i++) {
        int idx = tid + 256*i;
        int e = idx >> 6, j = idx & 63;
        float w = g_D1[idx] + s_q[e]*W1[12288 + idx];
        unsigned wh, wl; tf32_split(w, wh, wl);
        s_WbH[e*72 + j] = __uint_as_float(wh);
        s_WbL[e*72 + j] = __uint_as_float(wl);
    }
    // Stage hist rows R0..R0+127 (zeros past NT)
    #pragma unroll
    for (int i = 0; i < 8; i++) {
        int f4 = tid + 256*i;
        int r = f4 >> 4, e0 = (f4 & 15) << 2;
        int t = R0 + r;
        float4 v = (t < NT) ? *(const float4*)&hist[((size_t)(b*NT + t))*NE + e0]
                            : make_float4(0.f, 0.f, 0.f, 0.f);
        *(float4*)&s_h[r*68 + e0] = v;
    }
    __syncthreads();

    int w = tid >> 5, lane = tid & 31, g = lane >> 2, tin = lane & 3;
    int rg = w & 3, cg = w >> 2;            // rows rg*32, cols cg*32
    int rowbase = rg * 32;

    float d[2][4][4];
    #pragma unroll
    for (int mt = 0; mt < 2; mt++)
        #pragma unroll
        for (int j = 0; j < 4; j++)
            #pragma unroll
            for (int u = 0; u < 4; u++) d[mt][j][u] = 0.f;

    #pragma unroll
    for (int kt = 0; kt < 8; kt++) {
        int k0 = kt*8;
        unsigned ah[2][4];
        #pragma unroll
        for (int mt = 0; mt < 2; mt++) {
            int ar = (rowbase + mt*16 + g)*68 + k0 + tin;
            ah[mt][0] = tf32_of(s_h[ar]);
            ah[mt][1] = tf32_of(s_h[ar + 8*68]);
            ah[mt][2] = tf32_of(s_h[ar + 4]);
            ah[mt][3] = tf32_of(s_h[ar + 8*68 + 4]);
        }
        int brow0 = (k0 + tin)*72, brow1 = (k0 + tin + 4)*72;
        #pragma unroll
        for (int j = 0; j < 4; j++) {
            int n = cg*32 + j*8 + g;
            unsigned bh0 = __float_as_uint(s_WbH[brow0 + n]);
            unsigned bh1 = __float_as_uint(s_WbH[brow1 + n]);
            unsigned bl0 = __float_as_uint(s_WbL[brow0 + n]);
            unsigned bl1 = __float_as_uint(s_WbL[brow1 + n]);
            #pragma unroll
            for (int mt = 0; mt < 2; mt++) {
                MMA_TF32(d[mt][j], ah[mt][0],ah[mt][1],ah[mt][2],ah[mt][3], bh0,bh1);
                MMA_TF32(d[mt][j], ah[mt][0],ah[mt][1],ah[mt][2],ah[mt][3], bl0,bl1);
            }
        }
    }

    // epilogue: bias, store x1, stats (guards warp-uniform)
    #pragma unroll
    for (int mt = 0; mt < 2; mt++) {
        int base = R0 + rowbase + mt*16;
        bool okA = (base < NT);
        bool okB = (base + 8 < NT);
        if (okA) {
            int rA = base + g, rB = rA + 8;
            #pragma unroll
            for (int j = 0; j < 4; j++) {
                int c0 = cg*32 + j*8 + tin*2;
                float cb0 = s_cb[c0], cb1 = s_cb[c0+1];
                float v0 = d[mt][j][0] + cb0, v1 = d[mt][j][1] + cb1;
                float v2 = d[mt][j][2] + cb0, v3 = d[mt][j][3] + cb1;
                float sc0 = v0, sc1 = v1, qc0 = v0*v0, qc1 = v1*v1;
                *(float2*)&g_x1[(size_t)(b*NT + rA)*NH1 + c0] = make_float2(v0, v1);
                if (okB) {
                    *(float2*)&g_x1[(size_t)(b*NT + rB)*NH1 + c0] = make_float2(v2, v3);
                    sc0 += v2; sc1 += v3; qc0 += v2*v2; qc1 += v3*v3;
                }
                #pragma unroll
                for (int off = 4; off <= 16; off <<= 1) {
                    sc0 += __shfl_xor_sync(0xffffffffu, sc0, off);
                    sc1 += __shfl_xor_sync(0xffffffffu, sc1, off);
                    qc0 += __shfl_xor_sync(0xffffffffu, qc0, off);
                    qc1 += __shfl_xor_sync(0xffffffffu, qc1, off);
                }
                if (lane < 4) {
                    atomicAdd(&s_sum[c0],   sc0); atomicAdd(&s_sum[c0+1], sc1);
                    atomicAdd(&s_sq[c0],    qc0); atomicAdd(&s_sq[c0+1],  qc1);
                }
            }
        }
    }
    __syncthreads();
    if (tid < NH1) {
        atomicAdd(&g_sum1[tid], s_sum[tid]);
        atomicAdd(&g_sq1[tid],  s_sq[tid]);
    }
}

// ---------------------------------------------------------------------------
// Kernel B: x2 = dice1(x1) @ W2 + b2 (2-term TF32) + stats2. fin1 folded in.
// W2 in two planes [k][n] stride 24 (conflict-free loads). 128 rows/block.
// ---------------------------------------------------------------------------
__global__ __launch_bounds__(256, 4) void k_gemm2(
    const float* __restrict__ W2, const float* __restrict__ b2,
    const float* __restrict__ alpha1)
{
    __shared__ __align__(16) float s_x[128*68];     // fp32 dice1(x1) tile
    __shared__ float s_W2TH[64*24], s_W2TL[64*24];  // [k][n] planes
    __shared__ float s_m1[64], s_r1[64], s_a1[64], s_b2[16];
    __shared__ float s_sum[16], s_sq[16];

    int tid = threadIdx.x;
    int row0 = blockIdx.x * 128;
    if (tid < 64) {
        float nn = (float)NROWS;
        float m = g_sum1[tid] / nn;
        float v = g_sq1[tid] / nn - m*m;
        s_m1[tid] = m;
        s_r1[tid] = rsqrtf(v + 1e-8f);
        s_a1[tid] = alpha1[tid];
    }
    if (tid < 16) { s_b2[tid] = b2[tid]; s_sum[tid] = 0.f; s_sq[tid] = 0.f; }
    #pragma unroll
    for (int i = 0; i < 4; i++) {
        int idx = tid + 256*i;
        int k = idx >> 4, n = idx & 15;
        float wv = W2[idx];
        unsigned wh, wl; tf32_split(wv, wh, wl);
        s_W2TH[k*24 + n] = __uint_as_float(wh);
        s_W2TL[k*24 + n] = __uint_as_float(wl);
    }
    __syncthreads();

    // stage 128x64 x1 tile with dice1 applied (batched LDGs)
    #pragma unroll
    for (int bt = 0; bt < 4; bt++) {
        float4 vr[2];
        int f4b = tid + 256*(bt*2);
        #pragma unroll
        for (int u = 0; u < 2; u++) {
            int f4 = f4b + 256*u;
            int r = f4 >> 4, e0 = (f4 & 15) << 2;
            vr[u] = *(const float4*)&g_x1[(size_t)(row0 + r)*64 + e0];
        }
        #pragma unroll
        for (int u = 0; u < 2; u++) {
            int f4 = f4b + 256*u;
            int r = f4 >> 4, e0 = (f4 & 15) << 2;
            float vv[4] = {vr[u].x, vr[u].y, vr[u].z, vr[u].w};
            #pragma unroll
            for (int uu = 0; uu < 4; uu++) {
                int j = e0 + uu;
                float xn = (vv[uu] - s_m1[j]) * s_r1[j];
                float p  = __fdividef(1.f, 1.f + __expf(-xn));
                float a  = s_a1[j];
                vv[uu] = vv[uu] * (a + (1.f - a) * p);
            }
            *(float4*)&s_x[r*68 + e0] = make_float4(vv[0], vv[1], vv[2], vv[3]);
        }
    }
    __syncthreads();

    int w = tid >> 5, lane = tid & 31, g = lane >> 2, tin = lane & 3;
    int rg = w & 3, cg = w >> 2;          // rows rg*32, cols cg*8
    int rowbase = rg * 32;

    float d[2][4];
    #pragma unroll
    for (int mt = 0; mt < 2; mt++)
        #pragma unroll
        for (int u = 0; u < 4; u++) d[mt][u] = 0.f;

    #pragma unroll
    for (int kt = 0; kt < 8; kt++) {
        int k0 = kt*8;
        unsigned ah[2][4];
        #pragma unroll
        for (int mt = 0; mt < 2; mt++) {
            int ar = (rowbase + mt*16 + g)*68 + k0 + tin;
            ah[mt][0] = tf32_of(s_x[ar]);
            ah[mt][1] = tf32_of(s_x[ar + 8*68]);
            ah[mt][2] = tf32_of(s_x[ar + 4]);
            ah[mt][3] = tf32_of(s_x[ar + 8*68 + 4]);
        }
        int n = cg*8 + g;
        int brow0 = (k0 + tin)*24, brow1 = (k0 + tin + 4)*24;
        unsigned bh0 = __float_as_uint(s_W2TH[brow0 + n]);
        unsigned bh1 = __float_as_uint(s_W2TH[brow1 + n]);
        unsigned bl0 = __float_as_uint(s_W2TL[brow0 + n]);
        unsigned bl1 = __float_as_uint(s_W2TL[brow1 + n]);
        #pragma unroll
        for (int mt = 0; mt < 2; mt++) {
            MMA_TF32(d[mt], ah[mt][0],ah[mt][1],ah[mt][2],ah[mt][3], bh0,bh1);
            MMA_TF32(d[mt], ah[mt][0],ah[mt][1],ah[mt][2],ah[mt][3], bl0,bl1);
        }
    }

    #pragma unroll
    for (int mt = 0; mt < 2; mt++) {
        int rA = row0 + rowbase + mt*16 + g, rB = rA + 8;
        int c0 = cg*8 + tin*2;
        float b0v = s_b2[c0], b1v = s_b2[c0+1];
        float v0 = d[mt][0] + b0v, v1 = d[mt][1] + b1v;
        float v2 = d[mt][2] + b0v, v3 = d[mt][3] + b1v;
        *(float2*)&g_x2[(size_t)rA*16 + c0] = make_float2(v0, v1);
        *(float2*)&g_x2[(size_t)rB*16 + c0] = make_float2(v2, v3);
        float sc0 = v0 + v2, sc1 = v1 + v3;
        float qc0 = v0*v0 + v2*v2, qc1 = v1*v1 + v3*v3;
        #pragma unroll
        for (int off = 4; off <= 16; off <<= 1) {
            sc0 += __shfl_xor_sync(0xffffffffu, sc0, off);
            sc1 += __shfl_xor_sync(0xffffffffu, sc1, off);
            qc0 += __shfl_xor_sync(0xffffffffu, qc0, off);
            qc1 += __shfl_xor_sync(0xffffffffu, qc1, off);
        }
        if (lane < 4) {
            atomicAdd(&s_sum[c0],   sc0); atomicAdd(&s_sum[c0+1], sc1);
            atomicAdd(&s_sq[c0],    qc0); atomicAdd(&s_sq[c0+1],  qc1);
        }
    }
    __syncthreads();
    if (tid < 16) {
        atomicAdd(&g_sum2[tid], s_sum[tid]);
        atomicAdd(&g_sq2[tid],  s_sq[tid]);
    }
}

// ---------------------------------------------------------------------------
// Kernel C: dice2 -> mask -> softmax -> score @ hist (2-term TF32 MMA) -> out
// p tf32-rounded in single s_pH plane; hist staged [64][72] (conflict-free),
// B split in registers per k-step.
// ---------------------------------------------------------------------------
__global__ __launch_bounds__(256, 4) void k_final(
    const float* __restrict__ hist, const int* __restrict__ lens,
    const float* __restrict__ alpha2, float* __restrict__ out)
{
    __shared__ __align__(16) float s_pH[16][228];   // tf32-rounded p [h][t]
    __shared__ __align__(16) float s_hist[64][72];  // hist chunk [t][e]
    __shared__ float s_inv[16];
    __shared__ float s_m2[16], s_r2[16], s_a2[16];

    int b = blockIdx.x, tid = threadIdx.x;
    if (tid < 16) {
        float nn = (float)NROWS;
        float m = g_sum2[tid] / nn;
        float v = g_sq2[tid] / nn - m*m;
        s_m2[tid] = m;
        s_r2[tid] = rsqrtf(v + 1e-8f);
        s_a2[tid] = alpha2[tid];
    }
    __syncthreads();
    int len = lens[b];

    // stage logits with dice2 + mask into [h][t]
    #pragma unroll
    for (int i = 0; i < 4; i++) {
        int f4 = tid + 256*i;
        if (f4 < 800) {
            int r = f4 >> 2, h0 = (f4 & 3) << 2;
            float4 v = *(const float4*)&g_x2[(size_t)(b*NT + r)*16 + h0];
            float vv[4] = {v.x, v.y, v.z, v.w};
            #pragma unroll
            for (int u = 0; u < 4; u++) {
                int hh = h0 + u;
                float xn = (vv[u] - s_m2[hh]) * s_r2[hh];
                float p  = __fdividef(1.f, 1.f + __expf(-xn));
                float a  = s_a2[hh];
                float dd = vv[u] * (a + (1.f - a) * p);
                s_pH[hh][r] = (r < len) ? 1e-9f : dd;
            }
        }
    }
    __syncthreads();

    int w = tid >> 5, lane = tid & 31;
    // softmax: warp w handles h = 2w, 2w+1; store tf32-rounded exp, sum rounded
    #pragma unroll
    for (int hh = 0; hh < 2; hh++) {
        int h = 2*w + hh;
        float m = -1e30f;
        #pragma unroll
        for (int i = 0; i < 7; i++) {
            int t = lane + 32*i;
            if (t < NT) m = fmaxf(m, s_pH[h][t]);
        }
        #pragma unroll
        for (int off = 16; off >= 1; off >>= 1)
            m = fmaxf(m, __shfl_xor_sync(0xffffffffu, m, off));
        float s = 0.f;
        #pragma unroll
        for (int i = 0; i < 7; i++) {
            int t = lane + 32*i;
            if (t < NT) {
                float ev = __uint_as_float(tf32_of(__expf(s_pH[h][t] - m)));
                s_pH[h][t] = ev;
                s += ev;
            }
        }
        #pragma unroll
        for (int off = 16; off >= 1; off >>= 1)
            s += __shfl_xor_sync(0xffffffffu, s, off);
        if (lane == 0) s_inv[h] = __fdividef(1.f, s);
    }

    // out = (1/sum) * p[16x200] @ hist[200x64] via 2-term TF32 MMA
    int gq = lane >> 2, tin = lane & 3;
    int n0 = w * 8;
    float d[4] = {0.f, 0.f, 0.f, 0.f};

    for (int ck = 0; ck < 4; ck++) {
        __syncthreads();
        int rows = (ck < 3) ? 64 : 8;
        for (int f4 = tid; f4 < rows*16; f4 += 256) {
            int r = f4 >> 4, e0 = (f4 & 15) << 2;
            *(float4*)&s_hist[r][e0] =
                *(const float4*)&hist[(size_t)(b*NT + ck*64 + r)*64 + e0];
        }
        __syncthreads();
        int kts = rows >> 3;
        for (int kt = 0; kt < kts; kt++) {
            int k0 = kt*8, gk = ck*64 + k0;
            unsigned ah0 = __float_as_uint(s_pH[gq][gk + tin]);
            unsigned ah1 = __float_as_uint(s_pH[gq+8][gk + tin]);
            unsigned ah2 = __float_as_uint(s_pH[gq][gk + tin + 4]);
            unsigned ah3 = __float_as_uint(s_pH[gq+8][gk + tin + 4]);
            float b0f = s_hist[k0 + tin][n0 + gq];
            float b1f = s_hist[k0 + tin + 4][n0 + gq];
            unsigned bh0,bl0,bh1,bl1;
            tf32_split(b0f, bh0, bl0); tf32_split(b1f, bh1, bl1);
            MMA_TF32(d, ah0,ah1,ah2,ah3, bh0,bh1);
            MMA_TF32(d, ah0,ah1,ah2,ah3, bl0,bl1);
        }
    }

    float i0 = s_inv[gq], i1 = s_inv[gq + 8];
    int e0 = n0 + tin*2;
    *(float2*)&out[(size_t)(b*NH2 + gq    )*NE + e0] = make_float2(d[0]*i0, d[1]*i0);
    *(float2*)&out[(size_t)(b*NH2 + gq + 8)*NE + e0] = make_float2(d[2]*i1, d[3]*i1);
}

extern "C" void kernel_launch(void* const* d_in, const int* in_sizes, int n_in,
                              void* d_out, int out_size)
{
    const float* q    = (const float*)d_in[0];
    const float* hist = (const float*)d_in[1];
    const int*   lens = (const int*)  d_in[2];
    const float* W1   = (const float*)d_in[3];
    const float* b1   = (const float*)d_in[4];
    const float* a1   = (const float*)d_in[5];
    const float* W2   = (const float*)d_in[6];
    const float* b2   = (const float*)d_in[7];
    const float* a2   = (const float*)d_in[8];
    float* out = (float*)d_out;

    const int dyn1 = (128*68 + 2*64*72) * 4;   // 71680 B
    static int s_attr_done = 0;
    if (!s_attr_done) {
        cudaFuncSetAttribute(k_gemm1, cudaFuncAttributeMaxDynamicSharedMemorySize, dyn1);
        s_attr_done = 1;
    }

    k_zero<<<1, 64>>>();
    k_prep<<<NB/16, 256>>>(q, W1, b1);
    k_gemm1<<<2*NB, 256, dyn1>>>(q, hist, W1, b1);
    k_gemm2<<<NROWS/128, 256>>>(W2, b2, a1);
    k_final<<<NB, 256>>>(hist, lens, a2, out);
}

// round 16
// speedup vs baseline: 1.5486x; 1.0312x over previous
#include <cuda_runtime.h>
#include <cuda_fp16.h>
#include <math.h>

#define NB   2048
#define NT   200
#define NE   64
#define NH1  64
#define NH2  16
#define NROWS (NB*NT)

// Scratch (device globals; no allocation allowed)
__device__ __half g_x1h[(size_t)NROWS * NH1]; // [B*T, 64] fp16
__device__ __half g_x2h[(size_t)NROWS * NH2]; // [B*T, 16] fp16
__device__ float g_CB[(size_t)NB * NH1];      // per-batch effective bias
__device__ float g_D1[NE * NH1];              // W1b - W1c
__device__ float g_sum1[NH1], g_sq1[NH1];
__device__ float g_sum2[NH2], g_sq2[NH2];

__device__ __forceinline__ unsigned tf32_of(float f) {
    unsigned r;
    asm("cvt.rna.tf32.f32 %0, %1;" : "=r"(r) : "f"(f));
    return r;
}
__device__ __forceinline__ void tf32_split(float a, unsigned& hi, unsigned& lo) {
    hi = tf32_of(a);
    lo = tf32_of(a - __uint_as_float(hi));
}

#define MMA_TF32(d, a0,a1,a2,a3, b0,b1) \
    asm("mma.sync.aligned.m16n8k8.row.col.f32.tf32.tf32.f32 " \
        "{%0,%1,%2,%3}, {%4,%5,%6,%7}, {%8,%9}, {%0,%1,%2,%3};" \
        : "+f"(d[0]), "+f"(d[1]), "+f"(d[2]), "+f"(d[3]) \
        : "r"(a0), "r"(a1), "r"(a2), "r"(a3), "r"(b0), "r"(b1))

__global__ void k_zero() {
    int i = threadIdx.x;
    if (i < NH1) { g_sum1[i] = 0.f; g_sq1[i] = 0.f; }
    if (i < NH2) { g_sum2[i] = 0.f; g_sq2[i] = 0.f; }
}

// ---------------------------------------------------------------------------
// k_prep: CB[b][j] = b1[j] + sum_e q[b][e]*(W1a+W1c)[e][j]  for all batches;
// D1 = W1b - W1c. 128 blocks x 256 threads; 16 batches per block.
// ---------------------------------------------------------------------------
__global__ __launch_bounds__(256, 4) void k_prep(
    const float* __restrict__ q, const float* __restrict__ W1,
    const float* __restrict__ b1)
{
    __shared__ float s_S[64*64];     // (W1a + W1c)[e][j]
    __shared__ float s_qt[16*64];    // q rows for this block's batches

    int tid = threadIdx.x, bb0 = blockIdx.x * 16;

    if (blockIdx.x < 16) {
        int idx = blockIdx.x*256 + tid;
        g_D1[idx] = W1[4096 + idx] - W1[8192 + idx];
    }
    #pragma unroll
    for (int i = 0; i < 16; i++) {
        int idx = tid + 256*i;
        s_S[idx] = W1[idx] + W1[8192 + idx];
    }
    #pragma unroll
    for (int i = 0; i < 4; i++) {
        int idx = tid + 256*i;
        s_qt[idx] = q[(size_t)bb0*64 + idx];
    }
    __syncthreads();

    int j = tid & 63, bg = tid >> 6;          // thread -> (j, 4 batches)
    float acc[4] = {0.f, 0.f, 0.f, 0.f};
    #pragma unroll 8
    for (int e = 0; e < 64; e++) {
        float sv = s_S[e*64 + j];
        #pragma unroll
        for (int u = 0; u < 4; u++)
            acc[u] = fmaf(s_qt[(bg*4 + u)*64 + e], sv, acc[u]);
    }
    float bj = b1[j];
    #pragma unroll
    for (int u = 0; u < 4; u++)
        g_CB[(size_t)(bb0 + bg*4 + u)*64 + j] = acc[u] + bj;
}

// ---------------------------------------------------------------------------
// Kernel A: x1 = h@Wb + cb (2-term TF32), store x1 as fp16, stats1 in fp32.
// Wb = D1 + q*W1d; cb from g_CB. Wb in two planes [e][j] stride 72.
// Warp tile: 32 rows (rg) x 32 cols (cg). 2 blocks per batch.
// ---------------------------------------------------------------------------
__global__ __launch_bounds__(256, 3) void k_gemm1(
    const float* __restrict__ q, const float* __restrict__ hist,
    const float* __restrict__ W1, const float* __restrict__ b1)
{
    extern __shared__ __align__(16) float dsm[];
    float* s_h   = dsm;                       // [128][68] fp32 hist rows
    float* s_WbH = dsm + 128*68;              // [64][72] tf32-hi Wb (K-major)
    float* s_WbL = s_WbH + 64*72;             // [64][72] tf32-lo Wb
    __shared__ float s_q[NE], s_cb[NH1], s_sum[NH1], s_sq[NH1];

    int bid = blockIdx.x, tid = threadIdx.x;
    int b = bid >> 1, half = bid & 1;
    int R0 = half ? 128 : 0;

    if (tid < NE) {
        s_q[tid] = q[b*NE + tid];
        s_cb[tid] = g_CB[(size_t)b*64 + tid];
        s_sum[tid] = 0.f; s_sq[tid] = 0.f;
    }
    __syncthreads();

    // Build Wb = D1 + q*W1d, split into hi/lo planes (conflict-free stores)
    #pragma unroll
    for (int i = 0; i < 16; i++) {
        int idx = tid + 256*i;
        int e = idx >> 6, j = idx & 63;
        float w = g_D1[idx] + s_q[e]*W1[12288 + idx];
        unsigned wh, wl; tf32_split(w, wh, wl);
        s_WbH[e*72 + j] = __uint_as_float(wh);
        s_WbL[e*72 + j] = __uint_as_float(wl);
    }
    // Stage hist rows R0..R0+127 (zeros past NT)
    #pragma unroll
    for (int i = 0; i < 8; i++) {
        int f4 = tid + 256*i;
        int r = f4 >> 4, e0 = (f4 & 15) << 2;
        int t = R0 + r;
        float4 v = (t < NT) ? *(const float4*)&hist[((size_t)(b*NT + t))*NE + e0]
                            : make_float4(0.f, 0.f, 0.f, 0.f);
        *(float4*)&s_h[r*68 + e0] = v;
    }
    __syncthreads();

    int w = tid >> 5, lane = tid & 31, g = lane >> 2, tin = lane & 3;
    int rg = w & 3, cg = w >> 2;            // rows rg*32, cols cg*32
    int rowbase = rg * 32;

    float d[2][4][4];
    #pragma unroll
    for (int mt = 0; mt < 2; mt++)
        #pragma unroll
        for (int j = 0; j < 4; j++)
            #pragma unroll
            for (int u = 0; u < 4; u++) d[mt][j][u] = 0.f;

    #pragma unroll
    for (int kt = 0; kt < 8; kt++) {
        int k0 = kt*8;
        unsigned ah[2][4];
        #pragma unroll
        for (int mt = 0; mt < 2; mt++) {
            int ar = (rowbase + mt*16 + g)*68 + k0 + tin;
            ah[mt][0] = tf32_of(s_h[ar]);
            ah[mt][1] = tf32_of(s_h[ar + 8*68]);
            ah[mt][2] = tf32_of(s_h[ar + 4]);
            ah[mt][3] = tf32_of(s_h[ar + 8*68 + 4]);
        }
        int brow0 = (k0 + tin)*72, brow1 = (k0 + tin + 4)*72;
        #pragma unroll
        for (int j = 0; j < 4; j++) {
            int n = cg*32 + j*8 + g;
            unsigned bh0 = __float_as_uint(s_WbH[brow0 + n]);
            unsigned bh1 = __float_as_uint(s_WbH[brow1 + n]);
            unsigned bl0 = __float_as_uint(s_WbL[brow0 + n]);
            unsigned bl1 = __float_as_uint(s_WbL[brow1 + n]);
            #pragma unroll
            for (int mt = 0; mt < 2; mt++) {
                MMA_TF32(d[mt][j], ah[mt][0],ah[mt][1],ah[mt][2],ah[mt][3], bh0,bh1);
                MMA_TF32(d[mt][j], ah[mt][0],ah[mt][1],ah[mt][2],ah[mt][3], bl0,bl1);
            }
        }
    }

    // epilogue: bias, store x1 (fp16), stats in fp32 (guards warp-uniform)
    #pragma unroll
    for (int mt = 0; mt < 2; mt++) {
        int base = R0 + rowbase + mt*16;
        bool okA = (base < NT);
        bool okB = (base + 8 < NT);
        if (okA) {
            int rA = base + g, rB = rA + 8;
            #pragma unroll
            for (int j = 0; j < 4; j++) {
                int c0 = cg*32 + j*8 + tin*2;
                float cb0 = s_cb[c0], cb1 = s_cb[c0+1];
                float v0 = d[mt][j][0] + cb0, v1 = d[mt][j][1] + cb1;
                float v2 = d[mt][j][2] + cb0, v3 = d[mt][j][3] + cb1;
                float sc0 = v0, sc1 = v1, qc0 = v0*v0, qc1 = v1*v1;
                *(half2*)&g_x1h[(size_t)(b*NT + rA)*NH1 + c0] = __floats2half2_rn(v0, v1);
                if (okB) {
                    *(half2*)&g_x1h[(size_t)(b*NT + rB)*NH1 + c0] = __floats2half2_rn(v2, v3);
                    sc0 += v2; sc1 += v3; qc0 += v2*v2; qc1 += v3*v3;
                }
                #pragma unroll
                for (int off = 4; off <= 16; off <<= 1) {
                    sc0 += __shfl_xor_sync(0xffffffffu, sc0, off);
                    sc1 += __shfl_xor_sync(0xffffffffu, sc1, off);
                    qc0 += __shfl_xor_sync(0xffffffffu, qc0, off);
                    qc1 += __shfl_xor_sync(0xffffffffu, qc1, off);
                }
                if (lane < 4) {
                    atomicAdd(&s_sum[c0],   sc0); atomicAdd(&s_sum[c0+1], sc1);
                    atomicAdd(&s_sq[c0],    qc0); atomicAdd(&s_sq[c0+1],  qc1);
                }
            }
        }
    }
    __syncthreads();
    if (tid < NH1) {
        atomicAdd(&g_sum1[tid], s_sum[tid]);
        atomicAdd(&g_sq1[tid],  s_sq[tid]);
    }
}

// ---------------------------------------------------------------------------
// Kernel B: x2 = dice1(x1) @ W2 + b2 (2-term TF32) + stats2. fin1 folded in.
// x1 read as fp16 (uint4 = 8 halves per LDG). W2 in two planes [k][n] s24.
// ---------------------------------------------------------------------------
__global__ __launch_bounds__(256, 4) void k_gemm2(
    const float* __restrict__ W2, const float* __restrict__ b2,
    const float* __restrict__ alpha1)
{
    __shared__ __align__(16) float s_x[128*68];     // fp32 dice1(x1) tile
    __shared__ float s_W2TH[64*24], s_W2TL[64*24];  // [k][n] planes
    __shared__ float s_m1[64], s_r1[64], s_a1[64], s_b2[16];
    __shared__ float s_sum[16], s_sq[16];

    int tid = threadIdx.x;
    int row0 = blockIdx.x * 128;
    if (tid < 64) {
        float nn = (float)NROWS;
        float m = g_sum1[tid] / nn;
        float v = g_sq1[tid] / nn - m*m;
        s_m1[tid] = m;
        s_r1[tid] = rsqrtf(v + 1e-8f);
        s_a1[tid] = alpha1[tid];
    }
    if (tid < 16) { s_b2[tid] = b2[tid]; s_sum[tid] = 0.f; s_sq[tid] = 0.f; }
    #pragma unroll
    for (int i = 0; i < 4; i++) {
        int idx = tid + 256*i;
        int k = idx >> 4, n = idx & 15;
        float wv = W2[idx];
        unsigned wh, wl; tf32_split(wv, wh, wl);
        s_W2TH[k*24 + n] = __uint_as_float(wh);
        s_W2TL[k*24 + n] = __uint_as_float(wl);
    }
    __syncthreads();

    // stage 128x64 x1 tile (fp16 -> fp32 dice1), batched LDGs
    {
        uint4 raw[4];
        #pragma unroll
        for (int i = 0; i < 4; i++) {
            int f8 = tid + 256*i;
            int r = f8 >> 3, h0 = (f8 & 7) << 3;
            raw[i] = *(const uint4*)&g_x1h[(size_t)(row0 + r)*64 + h0];
        }
        #pragma unroll
        for (int i = 0; i < 4; i++) {
            int f8 = tid + 256*i;
            int r = f8 >> 3, h0 = (f8 & 7) << 3;
            half2* hp = (half2*)&raw[i];
            float vv[8];
            #pragma unroll
            for (int k = 0; k < 4; k++) {
                float2 f = __half22float2(hp[k]);
                vv[2*k] = f.x; vv[2*k+1] = f.y;
            }
            #pragma unroll
            for (int uu = 0; uu < 8; uu++) {
                int j = h0 + uu;
                float xn = (vv[uu] - s_m1[j]) * s_r1[j];
                float p  = __fdividef(1.f, 1.f + __expf(-xn));
                float a  = s_a1[j];
                vv[uu] = vv[uu] * (a + (1.f - a) * p);
            }
            *(float4*)&s_x[r*68 + h0]     = make_float4(vv[0], vv[1], vv[2], vv[3]);
            *(float4*)&s_x[r*68 + h0 + 4] = make_float4(vv[4], vv[5], vv[6], vv[7]);
        }
    }
    __syncthreads();

    int w = tid >> 5, lane = tid & 31, g = lane >> 2, tin = lane & 3;
    int rg = w & 3, cg = w >> 2;          // rows rg*32, cols cg*8
    int rowbase = rg * 32;

    float d[2][4];
    #pragma unroll
    for (int mt = 0; mt < 2; mt++)
        #pragma unroll
        for (int u = 0; u < 4; u++) d[mt][u] = 0.f;

    #pragma unroll
    for (int kt = 0; kt < 8; kt++) {
        int k0 = kt*8;
        unsigned ah[2][4];
        #pragma unroll
        for (int mt = 0; mt < 2; mt++) {
            int ar = (rowbase + mt*16 + g)*68 + k0 + tin;
            ah[mt][0] = tf32_of(s_x[ar]);
            ah[mt][1] = tf32_of(s_x[ar + 8*68]);
            ah[mt][2] = tf32_of(s_x[ar + 4]);
            ah[mt][3] = tf32_of(s_x[ar + 8*68 + 4]);
        }
        int n = cg*8 + g;
        int brow0 = (k0 + tin)*24, brow1 = (k0 + tin + 4)*24;
        unsigned bh0 = __float_as_uint(s_W2TH[brow0 + n]);
        unsigned bh1 = __float_as_uint(s_W2TH[brow1 + n]);
        unsigned bl0 = __float_as_uint(s_W2TL[brow0 + n]);
        unsigned bl1 = __float_as_uint(s_W2TL[brow1 + n]);
        #pragma unroll
        for (int mt = 0; mt < 2; mt++) {
            MMA_TF32(d[mt], ah[mt][0],ah[mt][1],ah[mt][2],ah[mt][3], bh0,bh1);
            MMA_TF32(d[mt], ah[mt][0],ah[mt][1],ah[mt][2],ah[mt][3], bl0,bl1);
        }
    }

    #pragma unroll
    for (int mt = 0; mt < 2; mt++) {
        int rA = row0 + rowbase + mt*16 + g, rB = rA + 8;
        int c0 = cg*8 + tin*2;
        float b0v = s_b2[c0], b1v = s_b2[c0+1];
        float v0 = d[mt][0] + b0v, v1 = d[mt][1] + b1v;
        float v2 = d[mt][2] + b0v, v3 = d[mt][3] + b1v;
        *(half2*)&g_x2h[(size_t)rA*16 + c0] = __floats2half2_rn(v0, v1);
        *(half2*)&g_x2h[(size_t)rB*16 + c0] = __floats2half2_rn(v2, v3);
        float sc0 = v0 + v2, sc1 = v1 + v3;
        float qc0 = v0*v0 + v2*v2, qc1 = v1*v1 + v3*v3;
        #pragma unroll
        for (int off = 4; off <= 16; off <<= 1) {
            sc0 += __shfl_xor_sync(0xffffffffu, sc0, off);
            sc1 += __shfl_xor_sync(0xffffffffu, sc1, off);
            qc0 += __shfl_xor_sync(0xffffffffu, qc0, off);
            qc1 += __shfl_xor_sync(0xffffffffu, qc1, off);
        }
        if (lane < 4) {
            atomicAdd(&s_sum[c0],   sc0); atomicAdd(&s_sum[c0+1], sc1);
            atomicAdd(&s_sq[c0],    qc0); atomicAdd(&s_sq[c0+1],  qc1);
        }
    }
    __syncthreads();
    if (tid < 16) {
        atomicAdd(&g_sum2[tid], s_sum[tid]);
        atomicAdd(&g_sq2[tid],  s_sq[tid]);
    }
}

// ---------------------------------------------------------------------------
// Kernel C: dice2 -> mask -> softmax -> score @ hist (2-term TF32 MMA) -> out
// x2 read as fp16 (uint4 = 8 halves). p tf32-rounded in single s_pH plane;
// hist staged [64][72].
// ---------------------------------------------------------------------------
__global__ __launch_bounds__(256, 4) void k_final(
    const float* __restrict__ hist, const int* __restrict__ lens,
    const float* __restrict__ alpha2, float* __restrict__ out)
{
    __shared__ __align__(16) float s_pH[16][228];   // tf32-rounded p [h][t]
    __shared__ __align__(16) float s_hist[64][72];  // hist chunk [t][e]
    __shared__ float s_inv[16];
    __shared__ float s_m2[16], s_r2[16], s_a2[16];

    int b = blockIdx.x, tid = threadIdx.x;
    if (tid < 16) {
        float nn = (float)NROWS;
        float m = g_sum2[tid] / nn;
        float v = g_sq2[tid] / nn - m*m;
        s_m2[tid] = m;
        s_r2[tid] = rsqrtf(v + 1e-8f);
        s_a2[tid] = alpha2[tid];
    }
    __syncthreads();
    int len = lens[b];

    // stage logits with dice2 + mask into [h][t] (fp16 x2, 8 halves/LDG)
    #pragma unroll
    for (int i = 0; i < 2; i++) {
        int f8 = tid + 256*i;
        if (f8 < 400) {
            int r = f8 >> 1, h0 = (f8 & 1) << 3;
            uint4 raw = *(const uint4*)&g_x2h[(size_t)(b*NT + r)*16 + h0];
            half2* hp = (half2*)&raw;
            #pragma unroll
            for (int k = 0; k < 4; k++) {
                float2 f = __half22float2(hp[k]);
                float vv[2] = {f.x, f.y};
                #pragma unroll
                for (int u = 0; u < 2; u++) {
                    int hh = h0 + 2*k + u;
                    float xn = (vv[u] - s_m2[hh]) * s_r2[hh];
                    float p  = __fdividef(1.f, 1.f + __expf(-xn));
                    float a  = s_a2[hh];
                    float dd = vv[u] * (a + (1.f - a) * p);
                    s_pH[hh][r] = (r < len) ? 1e-9f : dd;
                }
            }
        }
    }
    __syncthreads();

    int w = tid >> 5, lane = tid & 31;
    // softmax: warp w handles h = 2w, 2w+1; store tf32-rounded exp, sum rounded
    #pragma unroll
    for (int hh = 0; hh < 2; hh++) {
        int h = 2*w + hh;
        float m = -1e30f;
        #pragma unroll
        for (int i = 0; i < 7; i++) {
            int t = lane + 32*i;
            if (t < NT) m = fmaxf(m, s_pH[h][t]);
        }
        #pragma unroll
        for (int off = 16; off >= 1; off >>= 1)
            m = fmaxf(m, __shfl_xor_sync(0xffffffffu, m, off));
        float s = 0.f;
        #pragma unroll
        for (int i = 0; i < 7; i++) {
            int t = lane + 32*i;
            if (t < NT) {
                float ev = __uint_as_float(tf32_of(__expf(s_pH[h][t] - m)));
                s_pH[h][t] = ev;
                s += ev;
            }
        }
        #pragma unroll
        for (int off = 16; off >= 1; off >>= 1)
            s += __shfl_xor_sync(0xffffffffu, s, off);
        if (lane == 0) s_inv[h] = __fdividef(1.f, s);
    }

    // out = (1/sum) * p[16x200] @ hist[200x64] via 2-term TF32 MMA
    int gq = lane >> 2, tin = lane & 3;
    int n0 = w * 8;
    float d[4] = {0.f, 0.f, 0.f, 0.f};

    for (int ck = 0; ck < 4; ck++) {
        __syncthreads();
        int rows = (ck < 3) ? 64 : 8;
        for (int f4 = tid; f4 < rows*16; f4 += 256) {
            int r = f4 >> 4, e0 = (f4 & 15) << 2;
            *(float4*)&s_hist[r][e0] =
                *(const float4*)&hist[(size_t)(b*NT + ck*64 + r)*64 + e0];
        }
        __syncthreads();
        int kts = rows >> 3;
        for (int kt = 0; kt < kts; kt++) {
            int k0 = kt*8, gk = ck*64 + k0;
            unsigned ah0 = __float_as_uint(s_pH[gq][gk + tin]);
            unsigned ah1 = __float_as_uint(s_pH[gq+8][gk + tin]);
            unsigned ah2 = __float_as_uint(s_pH[gq][gk + tin + 4]);
            unsigned ah3 = __float_as_uint(s_pH[gq+8][gk + tin + 4]);
            float b0f = s_hist[k0 + tin][n0 + gq];
            float b1f = s_hist[k0 + tin + 4][n0 + gq];
            unsigned bh0,bl0,bh1,bl1;
            tf32_split(b0f, bh0, bl0); tf32_split(b1f, bh1, bl1);
            MMA_TF32(d, ah0,ah1,ah2,ah3, bh0,bh1);
            MMA_TF32(d, ah0,ah1,ah2,ah3, bl0,bl1);
        }
    }

    float i0 = s_inv[gq], i1 = s_inv[gq + 8];
    int e0 = n0 + tin*2;
    *(float2*)&out[(size_t)(b*NH2 + gq    )*NE + e0] = make_float2(d[0]*i0, d[1]*i0);
    *(float2*)&out[(size_t)(b*NH2 + gq + 8)*NE + e0] = make_float2(d[2]*i1, d[3]*i1);
}

extern "C" void kernel_launch(void* const* d_in, const int* in_sizes, int n_in,
                              void* d_out, int out_size)
{
    const float* q    = (const float*)d_in[0];
    const float* hist = (const float*)d_in[1];
    const int*   lens = (const int*)  d_in[2];
    const float* W1   = (const float*)d_in[3];
    const float* b1   = (const float*)d_in[4];
    const float* a1   = (const float*)d_in[5];
    const float* W2   = (const float*)d_in[6];
    const float* b2   = (const float*)d_in[7];
    const float* a2   = (const float*)d_in[8];
    float* out = (float*)d_out;

    const int dyn1 = (128*68 + 2*64*72) * 4;   // 71680 B
    static int s_attr_done = 0;
    if (!s_attr_done) {
        cudaFuncSetAttribute(k_gemm1, cudaFuncAttributeMaxDynamicSharedMemorySize, dyn1);
        s_attr_done = 1;
    }

    k_zero<<<1, 64>>>();
    k_prep<<<NB/16, 256>>>(q, W1, b1);
    k_gemm1<<<2*NB, 256, dyn1>>>(q, hist, W1, b1);
    k_gemm2<<<NROWS/128, 256>>>(W2, b2, a1);
    k_final<<<NB, 256>>>(hist, lens, a2, out);
}